// round 10
// baseline (speedup 1.0000x reference)
#include <cuda_runtime.h>
#include <cuda_fp16.h>
#include <math_constants.h>
#include <cstdint>

#define Bsz 4
#define Ssz 2048
#define Dm  1024
#define Hh  16
#define Dk  64
#define BH  (Bsz * Hh)
#define MD  ((size_t)8192 * 1024)
#define DD  ((size_t)1024 * 1024)

// ---------------- scratch (device globals; no allocation allowed) ----------
__device__ __align__(1024) __half g_qh[MD];            // Q hi (head-split)
__device__ __align__(1024) __half g_kh[MD];            // K hi
__device__ __align__(1024) __half g_kl[MD];            // K lo
__device__ __align__(1024) __half g_vh[MD];            // V hi
__device__ __align__(1024) __half g_ah[3 * MD];        // activations hi (q,k,v); slot0 reused for x
__device__ __align__(1024) __half g_wh[4 * DD];        // weights hi (Wq,Wk,Wv,Wo)
__device__ __align__(1024) __half g_wl[4 * DD];        // weights lo
__device__ __align__(1024) uint32_t g_mb[(size_t)Bsz * Ssz * (Ssz / 32)];

// ---------------- PTX helpers ----------------------------------------------
__device__ __forceinline__ uint32_t smem_u32(const void* p) {
    uint32_t a;
    asm("{ .reg .u64 t; cvta.to.shared.u64 t, %1; cvt.u32.u64 %0, t; }" : "=r"(a) : "l"(p));
    return a;
}
__device__ __forceinline__ void cp16(uint32_t dst, const void* src) {
    asm volatile("cp.async.cg.shared.global [%0], [%1], 16;" :: "r"(dst), "l"(src));
}
__device__ __forceinline__ void cp_commit() { asm volatile("cp.async.commit_group;"); }
__device__ __forceinline__ void cp_wait0()  { asm volatile("cp.async.wait_group 0;"); }
__device__ __forceinline__ void cp_wait1()  { asm volatile("cp.async.wait_group 1;"); }

__device__ __forceinline__ void ldsm4(uint32_t* r, uint32_t a) {
    asm volatile("ldmatrix.sync.aligned.m8n8.x4.shared.b16 {%0,%1,%2,%3}, [%4];"
                 : "=r"(r[0]), "=r"(r[1]), "=r"(r[2]), "=r"(r[3]) : "r"(a));
}
__device__ __forceinline__ void ldsm4t(uint32_t* r, uint32_t a) {
    asm volatile("ldmatrix.sync.aligned.m8n8.x4.trans.shared.b16 {%0,%1,%2,%3}, [%4];"
                 : "=r"(r[0]), "=r"(r[1]), "=r"(r[2]), "=r"(r[3]) : "r"(a));
}
__device__ __forceinline__ void mma16816(float* d, const uint32_t* a, const uint32_t* b) {
    asm volatile("mma.sync.aligned.m16n8k16.row.col.f32.f16.f16.f32 "
                 "{%0,%1,%2,%3}, {%4,%5,%6,%7}, {%8,%9}, {%0,%1,%2,%3};"
                 : "+f"(d[0]), "+f"(d[1]), "+f"(d[2]), "+f"(d[3])
                 : "r"(a[0]), "r"(a[1]), "r"(a[2]), "r"(a[3]), "r"(b[0]), "r"(b[1]));
}
__device__ __forceinline__ uint32_t pack_f16(float lo, float hi) {
    uint32_t r;
    asm("cvt.rn.f16x2.f32 %0, %1, %2;" : "=r"(r) : "f"(hi), "f"(lo));
    return r;
}
__device__ __forceinline__ void split2(float v0, float v1, uint32_t& hp, uint32_t& lp) {
    hp = pack_f16(v0, v1);
    __half2 h2 = *reinterpret_cast<__half2*>(&hp);
    float r0 = v0 - __half2float(h2.x);
    float r1 = v1 - __half2float(h2.y);
    lp = pack_f16(r0, r1);
}
__device__ __forceinline__ float qmax(float v) {
    v = fmaxf(v, __shfl_xor_sync(0xffffffffu, v, 1));
    v = fmaxf(v, __shfl_xor_sync(0xffffffffu, v, 2));
    return v;
}
__device__ __forceinline__ float qsum(float v) {
    v += __shfl_xor_sync(0xffffffffu, v, 1);
    v += __shfl_xor_sync(0xffffffffu, v, 2);
    return v;
}

// ---------------- fused fp32 -> fp16 conversions ----------------------------
__global__ __launch_bounds__(256)
void cvtW_kernel(const float* __restrict__ w0, const float* __restrict__ w1,
                 const float* __restrict__ w2, const float* __restrict__ w3)
{
    const int z = blockIdx.z;
    const float* src = (z == 0) ? w0 : (z == 1) ? w1 : (z == 2) ? w2 : w3;
    __half* hi = g_wh + (size_t)z * DD;
    __half* lo = g_wl + (size_t)z * DD;
    const int i = blockIdx.x * 256 + threadIdx.x;
    float4 v = ((const float4*)src)[i];
    uint32_t h0, l0, h1, l1;
    split2(v.x, v.y, h0, l0);
    split2(v.z, v.w, h1, l1);
    ((uint2*)hi)[i] = make_uint2(h0, h1);
    ((uint2*)lo)[i] = make_uint2(l0, l1);
}

__global__ __launch_bounds__(256)
void cvtA_kernel(const float* __restrict__ a0, const float* __restrict__ a1,
                 const float* __restrict__ a2)
{
    const int z = blockIdx.z;
    const float* src = (z == 0) ? a0 : (z == 1) ? a1 : a2;
    __half* hi = g_ah + (size_t)z * MD;
    const int i = blockIdx.x * 256 + threadIdx.x;
    float4 v = ((const float4*)src)[i];
    ((uint2*)hi)[i] = make_uint2(pack_f16(v.x, v.y), pack_f16(v.z, v.w));
}

// ---------------- mask -> bitmask pack --------------------------------------
__global__ __launch_bounds__(256)
void maskpack_kernel(const int* __restrict__ mask, uint32_t* __restrict__ bits)
{
    const int i = blockIdx.x * 256 + threadIdx.x;
    const uint32_t b = __ballot_sync(0xffffffffu, mask[i] != 0);
    if ((threadIdx.x & 31) == 0) bits[i >> 5] = b;
}

// ---------------- tensor-core 2-pass fp16 GEMM (3-stage, frag-pipelined) ----
#define GSTRIDE 80
#define GARR    10240
#define GSTAGE  30720            // 3 arrays (Ah, Wh, Wl)
#define GEMM_SMEM (3 * GSTAGE)   // 3 stages = 90 KB

__device__ __forceinline__ void gemm_load(uint32_t sb, int stage, int c, int tid,
                                          int m0, int n0,
                                          const __half* Ah, const __half* Wh, const __half* Wl)
{
#pragma unroll
    for (int it = 0; it < 6; it++) {
        const int flat = it * 256 + tid;                 // 0..1535
        const int arr = flat / 512, rem = flat & 511;
        const int row = rem >> 2, seg = rem & 3;
        const __half* src = (arr == 0) ? Ah : (arr == 1) ? Wh : Wl;
        const int gbase = (arr == 0) ? m0 : n0;
        cp16(sb + stage * GSTAGE + arr * GARR + row * GSTRIDE + seg * 16,
             src + (size_t)(gbase + row) * Dm + c * 32 + seg * 8);
    }
    cp_commit();
}

__device__ __forceinline__ void load_a_frag(uint32_t st, int wm, int lane, int kt,
                                            uint32_t af[2][4])
{
#pragma unroll
    for (int mt = 0; mt < 2; mt++) {
        const uint32_t ra = st +
            (uint32_t)(wm * 32 + mt * 16 + ((lane >> 3) & 1) * 8 + (lane & 7)) * GSTRIDE +
            kt * 32 + (lane >> 4) * 16;
        ldsm4(af[mt], ra);
    }
}
__device__ __forceinline__ void load_b_frag(uint32_t st, int wn, int lane, int kt, int hf,
                                            uint32_t bh[2][4], uint32_t bl[2][4])
{
#pragma unroll
    for (int j = 0; j < 2; j++) {
        const int nt2 = hf * 2 + j;
        const uint32_t rb = st + GARR +
            (uint32_t)(wn * 64 + nt2 * 16 + (lane >> 4) * 8 + (lane & 7)) * GSTRIDE +
            kt * 32 + ((lane >> 3) & 1) * 16;
        ldsm4(bh[j], rb);
        ldsm4(bl[j], rb + GARR);
    }
}

// MODE 0: output projection -> fp32 C.  MODE 1: per-z projection -> head-split fp16.
template <int MODE>
__global__ __launch_bounds__(256, 2)
void tgemm(const float* __restrict__ b0p, const float* __restrict__ b1p,
           const float* __restrict__ b2p, float* __restrict__ C)
{
    extern __shared__ char smem[];
    const uint32_t sb = smem_u32(smem);
    const int tid = threadIdx.x;
    const int lane = tid & 31, w = tid >> 5;
    const int wm = w >> 1, wn = w & 1;
    const int m0 = blockIdx.y * 128, n0 = blockIdx.x * 128;
    const int z = (MODE == 1) ? blockIdx.z : 3;

    const __half* Ah = g_ah + ((MODE == 1) ? (size_t)z * MD : 0);
    const __half* Wh = g_wh + (size_t)z * DD;
    const __half* Wl = g_wl + (size_t)z * DD;
    const float* bias = (MODE == 0) ? b0p : (z == 0) ? b0p : (z == 1) ? b1p : b2p;
    __half* Oh = (MODE == 1) ? ((z == 0) ? g_qh : (z == 1) ? g_kh : g_vh) : nullptr;

    float acc[2][8][4];
#pragma unroll
    for (int mt = 0; mt < 2; mt++)
#pragma unroll
        for (int nt = 0; nt < 8; nt++)
#pragma unroll
            for (int r = 0; r < 4; r++) acc[mt][nt][r] = 0.f;

    gemm_load(sb, 0, 0, tid, m0, n0, Ah, Wh, Wl);
    gemm_load(sb, 1, 1, tid, m0, n0, Ah, Wh, Wl);

    for (int c = 0; c < 32; c++) {
        if (c >= 30) cp_wait0(); else cp_wait1();
        __syncthreads();
        if (c + 2 < 32) gemm_load(sb, (c + 2) % 3, c + 2, tid, m0, n0, Ah, Wh, Wl);
        const uint32_t st = sb + (c % 3) * GSTAGE;

        // fragment-pipelined compute: 4 groups (kt x hf), double-buffered frags
        uint32_t a_buf[2][2][4];
        uint32_t bh_buf[2][2][4], bl_buf[2][2][4];
        load_a_frag(st, wm, lane, 0, a_buf[0]);
        load_b_frag(st, wn, lane, 0, 0, bh_buf[0], bl_buf[0]);
        int pb = 0;
#pragma unroll
        for (int g = 0; g < 4; g++) {
            const int kt = g >> 1, hf = g & 1;
            const int nb = pb ^ 1;
            if (g < 3) {
                const int ng = g + 1, nkt = ng >> 1, nhf = ng & 1;
                load_b_frag(st, wn, lane, nkt, nhf, bh_buf[nb], bl_buf[nb]);
                if (nkt != kt) load_a_frag(st, wm, lane, nkt, a_buf[nkt]);
            }
#pragma unroll
            for (int mt = 0; mt < 2; mt++)
#pragma unroll
                for (int j = 0; j < 2; j++) {
                    mma16816(acc[mt][(hf * 2 + j) * 2],     a_buf[kt][mt], bh_buf[pb][j]);
                    mma16816(acc[mt][(hf * 2 + j) * 2 + 1], a_buf[kt][mt], bh_buf[pb][j] + 2);
                }
#pragma unroll
            for (int mt = 0; mt < 2; mt++)
#pragma unroll
                for (int j = 0; j < 2; j++) {
                    mma16816(acc[mt][(hf * 2 + j) * 2],     a_buf[kt][mt], bl_buf[pb][j]);
                    mma16816(acc[mt][(hf * 2 + j) * 2 + 1], a_buf[kt][mt], bl_buf[pb][j] + 2);
                }
            pb = nb;
        }
    }

    const int grp = lane >> 2, qc = lane & 3;
#pragma unroll
    for (int mt = 0; mt < 2; mt++) {
#pragma unroll
        for (int nt = 0; nt < 8; nt++) {
            const int row = m0 + wm * 32 + mt * 16 + grp;
            const int col = n0 + wn * 64 + nt * 8 + qc * 2;
            const float b0 = bias[col], b1 = bias[col + 1];
            const float v0 = acc[mt][nt][0] + b0, v1 = acc[mt][nt][1] + b1;
            const float v2 = acc[mt][nt][2] + b0, v3 = acc[mt][nt][3] + b1;
            if (MODE == 0) {
                *(float2*)&C[(size_t)row * Dm + col]       = make_float2(v0, v1);
                *(float2*)&C[(size_t)(row + 8) * Dm + col] = make_float2(v2, v3);
            } else {
                const int hh = col >> 6, dk = col & 63;
#pragma unroll
                for (int half_i = 0; half_i < 2; half_i++) {
                    const int r2 = row + half_i * 8;
                    const int bb = r2 >> 11, s = r2 & 2047;
                    const size_t idx = (((size_t)(bb * Hh + hh)) * Ssz + s) * Dk + dk;
                    const float x0 = half_i ? v2 : v0, x1 = half_i ? v3 : v1;
                    if (z == 1) {          // K keeps hi+lo (QK 2-pass uses K-lo)
                        uint32_t hp, lp; split2(x0, x1, hp, lp);
                        *(uint32_t*)&Oh[idx] = hp;
                        *(uint32_t*)&g_kl[idx] = lp;
                    } else {               // Q, V: hi only
                        *(uint32_t*)&Oh[idx] = pack_f16(x0, x1);
                    }
                }
            }
        }
    }
}

// ---------------- flash attention: fp16, 2-pass QK, 1-pass PV ---------------
#define FQ 128
#define FK 64
#define FSTR 144
#define QH_OFF 0
#define KV_OFF 18432
#define KVST   27648            // per stage: kh, kl, vh (9216 each)
#define KL_O 9216
#define VH_O 18432
#define FLASH_SMEM 73728        // 72 KB -> 2 CTAs/SM

__device__ __forceinline__ void flash_load_kv(uint32_t sb, int j, int tid, size_t bh)
{
#pragma unroll
    for (int it = 0; it < 6; it++) {
        const int flat = it * 256 + tid;                 // 0..1535
        const int arr = flat / 512, rem = flat & 511;
        const int row = rem >> 3, seg = rem & 7;
        const __half* src = (arr == 0) ? g_kh : (arr == 1) ? g_kl : g_vh;
        cp16(sb + KV_OFF + (j & 1) * KVST + arr * 9216 + row * FSTR + seg * 16,
             src + (bh * Ssz + j * FK + row) * Dk + seg * 8);
    }
    cp_commit();
}

__global__ __launch_bounds__(256, 2)
void flash(const uint32_t* __restrict__ mb, __half* __restrict__ xh)
{
    extern __shared__ char smem[];
    const uint32_t sb = smem_u32(smem);
    const int tid = threadIdx.x, lane = tid & 31, w = tid >> 5;
    const int b = blockIdx.z, h = blockIdx.y, q0 = blockIdx.x * FQ;
    const size_t bh = (size_t)(b * Hh + h);
    const int grp = lane >> 2, qc = lane & 3;
    const int row_a = q0 + w * 16 + grp;

    flash_load_kv(sb, 0, tid, bh);
#pragma unroll
    for (int it = 0; it < 4; it++) {
        const int flat = it * 256 + tid;                 // 0..1023
        const int row = flat >> 3, seg = flat & 7;
        cp16(sb + QH_OFF + row * FSTR + seg * 16,
             g_qh + (bh * Ssz + q0 + row) * Dk + seg * 8);
    }
    cp_commit();
    cp_wait0();
    __syncthreads();

    // hoist loop-invariant Q-hi fragments
    const uint32_t qrow = (uint32_t)(w * 16 + ((lane >> 3) & 1) * 8 + (lane & 7)) * FSTR +
                          (lane >> 4) * 16;
    uint32_t qfh[4][4];
#pragma unroll
    for (int kt = 0; kt < 4; kt++) ldsm4(qfh[kt], sb + QH_OFF + qrow + kt * 32);

    float acc_o[8][4];
#pragma unroll
    for (int nt = 0; nt < 8; nt++)
#pragma unroll
        for (int r = 0; r < 4; r++) acc_o[nt][r] = 0.f;
    float m_a = -CUDART_INF_F, m_b = -CUDART_INF_F, l_a = 0.f, l_b = 0.f;

    const uint32_t* mrow_a = mb + ((size_t)b * Ssz + row_a) * (Ssz / 32);
    const uint32_t* mrow_b = mrow_a + 8 * (Ssz / 32);

    const int NJT = Ssz / FK;   // 32
    for (int jt = 0; jt < NJT; jt++) {
        const uint2 wa = *(const uint2*)(mrow_a + jt * 2);
        const uint2 wb = *(const uint2*)(mrow_b + jt * 2);
        if (jt > 0) { cp_wait0(); __syncthreads(); }
        if (jt + 1 < NJT) flash_load_kv(sb, jt + 1, tid, bh);
        const uint32_t st = sb + KV_OFF + (jt & 1) * KVST;

        // ---- QK^T: Qh·Kh + Qh·Kl (2-pass) ----
        float s[8][4];
#pragma unroll
        for (int nt = 0; nt < 8; nt++)
#pragma unroll
            for (int r = 0; r < 4; r++) s[nt][r] = 0.f;
#pragma unroll
        for (int kt = 0; kt < 4; kt++) {
#pragma unroll
            for (int hf = 0; hf < 2; hf++) {
                uint32_t b_h[2][4], b_l[2][4];
#pragma unroll
                for (int j = 0; j < 2; j++) {
                    const int nt2 = hf * 2 + j;
                    const uint32_t rb = st +
                        (uint32_t)(nt2 * 16 + (lane >> 4) * 8 + (lane & 7)) * FSTR +
                        kt * 32 + ((lane >> 3) & 1) * 16;
                    ldsm4(b_h[j], rb);
                    ldsm4(b_l[j], rb + KL_O);
                }
#pragma unroll
                for (int j = 0; j < 2; j++) {
                    mma16816(s[(hf * 2 + j) * 2],     qfh[kt], b_h[j]);
                    mma16816(s[(hf * 2 + j) * 2 + 1], qfh[kt], b_h[j] + 2);
                }
#pragma unroll
                for (int j = 0; j < 2; j++) {
                    mma16816(s[(hf * 2 + j) * 2],     qfh[kt], b_l[j]);
                    mma16816(s[(hf * 2 + j) * 2 + 1], qfh[kt], b_l[j] + 2);
                }
            }
        }

        // ---- scale + mask + online softmax (fp32 exp, fp32 sums) ----
        float ra = -CUDART_INF_F, rbx = -CUDART_INF_F;
#pragma unroll
        for (int nt = 0; nt < 8; nt++) {
            const int kk = nt * 8 + qc * 2;
            const uint32_t wA = (nt < 4) ? wa.x : wa.y;
            const uint32_t wB = (nt < 4) ? wb.x : wb.y;
            const int bit = kk & 31;
            s[nt][0] = ((wA >> bit) & 1)       ? s[nt][0] * 0.125f : -1e9f;
            s[nt][1] = ((wA >> (bit + 1)) & 1) ? s[nt][1] * 0.125f : -1e9f;
            s[nt][2] = ((wB >> bit) & 1)       ? s[nt][2] * 0.125f : -1e9f;
            s[nt][3] = ((wB >> (bit + 1)) & 1) ? s[nt][3] * 0.125f : -1e9f;
            ra  = fmaxf(ra,  fmaxf(s[nt][0], s[nt][1]));
            rbx = fmaxf(rbx, fmaxf(s[nt][2], s[nt][3]));
        }
        ra = qmax(ra); rbx = qmax(rbx);
        const float mna = fmaxf(m_a, ra), mnb = fmaxf(m_b, rbx);
        const float ca = __expf(m_a - mna), cb = __expf(m_b - mnb);
        float suma = 0.f, sumb = 0.f;
#pragma unroll
        for (int nt = 0; nt < 8; nt++) {
            s[nt][0] = __expf(s[nt][0] - mna);
            s[nt][1] = __expf(s[nt][1] - mna);
            s[nt][2] = __expf(s[nt][2] - mnb);
            s[nt][3] = __expf(s[nt][3] - mnb);
            suma += s[nt][0] + s[nt][1];
            sumb += s[nt][2] + s[nt][3];
        }
        l_a = l_a * ca + qsum(suma);
        l_b = l_b * cb + qsum(sumb);
#pragma unroll
        for (int nt = 0; nt < 8; nt++) {
            acc_o[nt][0] *= ca; acc_o[nt][1] *= ca;
            acc_o[nt][2] *= cb; acc_o[nt][3] *= cb;
        }
        m_a = mna; m_b = mnb;

        // ---- P @ V: single pass, P rounded to fp16 in registers ----
#pragma unroll
        for (int kt2 = 0; kt2 < 4; kt2++) {
            uint32_t p_h[4];
            p_h[0] = pack_f16(s[2 * kt2][0],     s[2 * kt2][1]);
            p_h[1] = pack_f16(s[2 * kt2][2],     s[2 * kt2][3]);
            p_h[2] = pack_f16(s[2 * kt2 + 1][0], s[2 * kt2 + 1][1]);
            p_h[3] = pack_f16(s[2 * kt2 + 1][2], s[2 * kt2 + 1][3]);
#pragma unroll
            for (int hf = 0; hf < 2; hf++) {
                uint32_t v_h[2][4];
#pragma unroll
                for (int j = 0; j < 2; j++) {
                    const int nd2 = hf * 2 + j;
                    const uint32_t vb = st + VH_O +
                        (uint32_t)(kt2 * 16 + ((lane >> 3) & 1) * 8 + (lane & 7)) * FSTR +
                        nd2 * 32 + (lane >> 4) * 16;
                    ldsm4t(v_h[j], vb);
                }
#pragma unroll
                for (int j = 0; j < 2; j++) {
                    mma16816(acc_o[(hf * 2 + j) * 2],     p_h, v_h[j]);
                    mma16816(acc_o[(hf * 2 + j) * 2 + 1], p_h, v_h[j] + 2);
                }
            }
        }
    }

    // epilogue: x hi-only fp16
    const float inva = 1.f / l_a, invb = 1.f / l_b;
#pragma unroll
    for (int nt = 0; nt < 8; nt++) {
        const int col = h * Dk + nt * 8 + qc * 2;
        size_t idx = ((size_t)b * Ssz + row_a) * Dm + col;
        *(uint32_t*)&xh[idx] = pack_f16(acc_o[nt][0] * inva, acc_o[nt][1] * inva);
        idx = ((size_t)b * Ssz + row_a + 8) * Dm + col;
        *(uint32_t*)&xh[idx] = pack_f16(acc_o[nt][2] * invb, acc_o[nt][3] * invb);
    }
}

// ---------------- launch ----------------------------------------------------
extern "C" void kernel_launch(void* const* d_in, const int* in_sizes, int n_in,
                              void* d_out, int out_size)
{
    (void)in_sizes; (void)n_in; (void)out_size;
    const float* query  = (const float*)d_in[0];
    const float* key_in = (const float*)d_in[1];
    const float* value  = (const float*)d_in[2];
    const int*   mask   = (const int*)  d_in[3];
    const float* Wq = (const float*)d_in[4];
    const float* bq = (const float*)d_in[5];
    const float* Wk = (const float*)d_in[6];
    const float* bk = (const float*)d_in[7];
    const float* Wv = (const float*)d_in[8];
    const float* bv = (const float*)d_in[9];
    const float* Wo = (const float*)d_in[10];
    const float* bo = (const float*)d_in[11];
    float* out = (float*)d_out;

    __half* ah;
    uint32_t* mbp;
    cudaGetSymbolAddress((void**)&ah, g_ah);
    cudaGetSymbolAddress((void**)&mbp, g_mb);

    cudaFuncSetAttribute(tgemm<0>, cudaFuncAttributeMaxDynamicSharedMemorySize, GEMM_SMEM);
    cudaFuncSetAttribute(tgemm<1>, cudaFuncAttributeMaxDynamicSharedMemorySize, GEMM_SMEM);
    cudaFuncSetAttribute(flash, cudaFuncAttributeMaxDynamicSharedMemorySize, FLASH_SMEM);

    // mask pack
    maskpack_kernel<<<(Bsz * Ssz * Ssz) / 256, 256>>>(mask, mbp);
    // fused conversions
    dim3 wgrid((Dm * Dm / 4) / 256, 1, 4);
    cvtW_kernel<<<wgrid, 256>>>(Wq, Wk, Wv, Wo);
    dim3 agrid((int)((MD / 4) / 256), 1, 3);
    cvtA_kernel<<<agrid, 256>>>(query, key_in, value);
    // fused Q/K/V projections
    dim3 pgrid(Dm / 128, 8192 / 128, 3);
    tgemm<1><<<pgrid, 256, GEMM_SMEM>>>(bq, bk, bv, nullptr);
    // attention (x hi -> activation slot 0)
    dim3 fgrid(Ssz / FQ, Hh, Bsz);
    flash<<<fgrid, 256, FLASH_SMEM>>>(mbp, ah);
    // output projection
    dim3 ogrid(Dm / 128, 8192 / 128);
    tgemm<0><<<ogrid, 256, GEMM_SMEM>>>(bo, nullptr, nullptr, out);
}

// round 11
// speedup vs baseline: 1.0217x; 1.0217x over previous
#include <cuda_runtime.h>
#include <cuda_fp16.h>
#include <math_constants.h>
#include <cstdint>

#define Bsz 4
#define Ssz 2048
#define Dm  1024
#define Hh  16
#define Dk  64
#define BH  (Bsz * Hh)
#define MD  ((size_t)8192 * 1024)
#define DD  ((size_t)1024 * 1024)

// ---------------- scratch (device globals; no allocation allowed) ----------
__device__ __align__(1024) __half g_qh[MD];            // Q hi (head-split)
__device__ __align__(1024) __half g_kh[MD];            // K hi
__device__ __align__(1024) __half g_kl[MD];            // K lo
__device__ __align__(1024) __half g_vh[MD];            // V hi
__device__ __align__(1024) __half g_ah[3 * MD];        // activations hi (q,k,v); slot0 reused for x
__device__ __align__(1024) __half g_wh[4 * DD];        // weights hi (Wq,Wk,Wv,Wo)
__device__ __align__(1024) __half g_wl[4 * DD];        // weights lo
__device__ __align__(1024) uint32_t g_mb[(size_t)Bsz * Ssz * (Ssz / 32)];

// ---------------- PTX helpers ----------------------------------------------
__device__ __forceinline__ uint32_t smem_u32(const void* p) {
    uint32_t a;
    asm("{ .reg .u64 t; cvta.to.shared.u64 t, %1; cvt.u32.u64 %0, t; }" : "=r"(a) : "l"(p));
    return a;
}
__device__ __forceinline__ void cp16(uint32_t dst, const void* src) {
    asm volatile("cp.async.cg.shared.global [%0], [%1], 16;" :: "r"(dst), "l"(src));
}
__device__ __forceinline__ void cp_commit() { asm volatile("cp.async.commit_group;"); }
__device__ __forceinline__ void cp_wait0()  { asm volatile("cp.async.wait_group 0;"); }

__device__ __forceinline__ void ldsm4(uint32_t* r, uint32_t a) {
    asm volatile("ldmatrix.sync.aligned.m8n8.x4.shared.b16 {%0,%1,%2,%3}, [%4];"
                 : "=r"(r[0]), "=r"(r[1]), "=r"(r[2]), "=r"(r[3]) : "r"(a));
}
__device__ __forceinline__ void ldsm4t(uint32_t* r, uint32_t a) {
    asm volatile("ldmatrix.sync.aligned.m8n8.x4.trans.shared.b16 {%0,%1,%2,%3}, [%4];"
                 : "=r"(r[0]), "=r"(r[1]), "=r"(r[2]), "=r"(r[3]) : "r"(a));
}
__device__ __forceinline__ void mma16816(float* d, const uint32_t* a, const uint32_t* b) {
    asm volatile("mma.sync.aligned.m16n8k16.row.col.f32.f16.f16.f32 "
                 "{%0,%1,%2,%3}, {%4,%5,%6,%7}, {%8,%9}, {%0,%1,%2,%3};"
                 : "+f"(d[0]), "+f"(d[1]), "+f"(d[2]), "+f"(d[3])
                 : "r"(a[0]), "r"(a[1]), "r"(a[2]), "r"(a[3]), "r"(b[0]), "r"(b[1]));
}
__device__ __forceinline__ uint32_t pack_f16(float lo, float hi) {
    uint32_t r;
    asm("cvt.rn.f16x2.f32 %0, %1, %2;" : "=r"(r) : "f"(hi), "f"(lo));
    return r;
}
__device__ __forceinline__ void split2(float v0, float v1, uint32_t& hp, uint32_t& lp) {
    hp = pack_f16(v0, v1);
    __half2 h2 = *reinterpret_cast<__half2*>(&hp);
    float r0 = v0 - __half2float(h2.x);
    float r1 = v1 - __half2float(h2.y);
    lp = pack_f16(r0, r1);
}
__device__ __forceinline__ float qmax(float v) {
    v = fmaxf(v, __shfl_xor_sync(0xffffffffu, v, 1));
    v = fmaxf(v, __shfl_xor_sync(0xffffffffu, v, 2));
    return v;
}
__device__ __forceinline__ float qsum(float v) {
    v += __shfl_xor_sync(0xffffffffu, v, 1);
    v += __shfl_xor_sync(0xffffffffu, v, 2);
    return v;
}

// ---------------- fused fp32 -> fp16 conversions ----------------------------
__global__ __launch_bounds__(256)
void cvtW_kernel(const float* __restrict__ w0, const float* __restrict__ w1,
                 const float* __restrict__ w2, const float* __restrict__ w3)
{
    const int z = blockIdx.z;
    const float* src = (z == 0) ? w0 : (z == 1) ? w1 : (z == 2) ? w2 : w3;
    __half* hi = g_wh + (size_t)z * DD;
    __half* lo = g_wl + (size_t)z * DD;
    const int i = blockIdx.x * 256 + threadIdx.x;
    float4 v = ((const float4*)src)[i];
    uint32_t h0, l0, h1, l1;
    split2(v.x, v.y, h0, l0);
    split2(v.z, v.w, h1, l1);
    ((uint2*)hi)[i] = make_uint2(h0, h1);
    ((uint2*)lo)[i] = make_uint2(l0, l1);
}

__global__ __launch_bounds__(256)
void cvtA_kernel(const float* __restrict__ a0, const float* __restrict__ a1,
                 const float* __restrict__ a2)
{
    const int z = blockIdx.z;
    const float* src = (z == 0) ? a0 : (z == 1) ? a1 : a2;
    __half* hi = g_ah + (size_t)z * MD;
    const int i = blockIdx.x * 256 + threadIdx.x;
    float4 v = ((const float4*)src)[i];
    ((uint2*)hi)[i] = make_uint2(pack_f16(v.x, v.y), pack_f16(v.z, v.w));
}

// ---------------- mask -> bitmask pack --------------------------------------
__global__ __launch_bounds__(256)
void maskpack_kernel(const int* __restrict__ mask, uint32_t* __restrict__ bits)
{
    const int i = blockIdx.x * 256 + threadIdx.x;
    const uint32_t b = __ballot_sync(0xffffffffu, mask[i] != 0);
    if ((threadIdx.x & 31) == 0) bits[i >> 5] = b;
}

// ---------------- tensor-core 2-pass fp16 GEMM ------------------------------
// 64x128 CTA tile, 128 threads (4 warps, 2x2), BK=32, 2-stage, 4 CTAs/SM.
#define GSTRIDE 80
#define A_ROWS  64
#define A_BYTES (A_ROWS * GSTRIDE)          // 5120
#define W_BYTES (128 * GSTRIDE)             // 10240
#define GSTAGE  (A_BYTES + 2 * W_BYTES)     // 25600
#define GEMM_SMEM (2 * GSTAGE)              // 51200 -> 4 CTAs/SM

__device__ __forceinline__ void gemm_load(uint32_t sb, int stage, int c, int tid,
                                          int m0, int n0,
                                          const __half* Ah, const __half* Wh, const __half* Wl)
{
    // 1280 cp16 per stage: Ah 256 (64 rows x 4 segs), Wh 512, Wl 512
#pragma unroll
    for (int it = 0; it < 10; it++) {
        const int flat = it * 128 + tid;                 // 0..1279
        int arr, rem, base;
        if (flat < 256)      { arr = 0; rem = flat;       base = 0; }
        else if (flat < 768) { arr = 1; rem = flat - 256; base = A_BYTES; }
        else                 { arr = 2; rem = flat - 768; base = A_BYTES + W_BYTES; }
        const int row = rem >> 2, seg = rem & 3;
        const __half* src = (arr == 0) ? Ah : (arr == 1) ? Wh : Wl;
        const int gbase = (arr == 0) ? m0 : n0;
        cp16(sb + stage * GSTAGE + base + row * GSTRIDE + seg * 16,
             src + (size_t)(gbase + row) * Dm + c * 32 + seg * 8);
    }
    cp_commit();
}

// MODE 0: output projection -> fp32 C.  MODE 1: per-z projection -> head-split fp16.
template <int MODE>
__global__ __launch_bounds__(128, 4)
void tgemm(const float* __restrict__ b0p, const float* __restrict__ b1p,
           const float* __restrict__ b2p, float* __restrict__ C)
{
    extern __shared__ char smem[];
    const uint32_t sb = smem_u32(smem);
    const int tid = threadIdx.x;
    const int lane = tid & 31, w = tid >> 5;
    const int wm = w >> 1, wn = w & 1;                  // 2x2 warp grid, warp tile 32x64
    const int m0 = blockIdx.y * 64, n0 = blockIdx.x * 128;
    const int z = (MODE == 1) ? blockIdx.z : 3;

    const __half* Ah = g_ah + ((MODE == 1) ? (size_t)z * MD : 0);
    const __half* Wh = g_wh + (size_t)z * DD;
    const __half* Wl = g_wl + (size_t)z * DD;
    const float* bias = (MODE == 0) ? b0p : (z == 0) ? b0p : (z == 1) ? b1p : b2p;
    __half* Oh = (MODE == 1) ? ((z == 0) ? g_qh : (z == 1) ? g_kh : g_vh) : nullptr;

    float acc[2][8][4];
#pragma unroll
    for (int mt = 0; mt < 2; mt++)
#pragma unroll
        for (int nt = 0; nt < 8; nt++)
#pragma unroll
            for (int r = 0; r < 4; r++) acc[mt][nt][r] = 0.f;

    gemm_load(sb, 0, 0, tid, m0, n0, Ah, Wh, Wl);

    for (int c = 0; c < 32; c++) {
        cp_wait0();
        __syncthreads();
        if (c + 1 < 32) gemm_load(sb, (c + 1) & 1, c + 1, tid, m0, n0, Ah, Wh, Wl);
        const uint32_t st = sb + (c & 1) * GSTAGE;
#pragma unroll
        for (int kt = 0; kt < 2; kt++) {
            uint32_t a_h[2][4];
#pragma unroll
            for (int mt = 0; mt < 2; mt++) {
                const uint32_t ra = st +
                    (uint32_t)(wm * 32 + mt * 16 + ((lane >> 3) & 1) * 8 + (lane & 7)) * GSTRIDE +
                    kt * 32 + (lane >> 4) * 16;
                ldsm4(a_h[mt], ra);
            }
#pragma unroll
            for (int hf = 0; hf < 2; hf++) {
                uint32_t b_h[2][4], b_l[2][4];
#pragma unroll
                for (int j = 0; j < 2; j++) {
                    const int nt2 = hf * 2 + j;
                    const uint32_t rb = st + A_BYTES +
                        (uint32_t)(wn * 64 + nt2 * 16 + (lane >> 4) * 8 + (lane & 7)) * GSTRIDE +
                        kt * 32 + ((lane >> 3) & 1) * 16;
                    ldsm4(b_h[j], rb);
                    ldsm4(b_l[j], rb + W_BYTES);
                }
#pragma unroll
                for (int mt = 0; mt < 2; mt++)
#pragma unroll
                    for (int j = 0; j < 2; j++) {
                        mma16816(acc[mt][(hf * 2 + j) * 2],     a_h[mt], b_h[j]);
                        mma16816(acc[mt][(hf * 2 + j) * 2 + 1], a_h[mt], b_h[j] + 2);
                    }
#pragma unroll
                for (int mt = 0; mt < 2; mt++)
#pragma unroll
                    for (int j = 0; j < 2; j++) {
                        mma16816(acc[mt][(hf * 2 + j) * 2],     a_h[mt], b_l[j]);
                        mma16816(acc[mt][(hf * 2 + j) * 2 + 1], a_h[mt], b_l[j] + 2);
                    }
            }
        }
    }

    const int grp = lane >> 2, qc = lane & 3;
#pragma unroll
    for (int mt = 0; mt < 2; mt++) {
#pragma unroll
        for (int nt = 0; nt < 8; nt++) {
            const int row = m0 + wm * 32 + mt * 16 + grp;
            const int col = n0 + wn * 64 + nt * 8 + qc * 2;
            const float b0 = bias[col], b1 = bias[col + 1];
            const float v0 = acc[mt][nt][0] + b0, v1 = acc[mt][nt][1] + b1;
            const float v2 = acc[mt][nt][2] + b0, v3 = acc[mt][nt][3] + b1;
            if (MODE == 0) {
                *(float2*)&C[(size_t)row * Dm + col]       = make_float2(v0, v1);
                *(float2*)&C[(size_t)(row + 8) * Dm + col] = make_float2(v2, v3);
            } else {
                const int hh = col >> 6, dk = col & 63;
#pragma unroll
                for (int half_i = 0; half_i < 2; half_i++) {
                    const int r2 = row + half_i * 8;
                    const int bb = r2 >> 11, s = r2 & 2047;
                    const size_t idx = (((size_t)(bb * Hh + hh)) * Ssz + s) * Dk + dk;
                    const float x0 = half_i ? v2 : v0, x1 = half_i ? v3 : v1;
                    if (z == 1) {          // K keeps hi+lo (QK 2-pass uses K-lo)
                        uint32_t hp, lp; split2(x0, x1, hp, lp);
                        *(uint32_t*)&Oh[idx] = hp;
                        *(uint32_t*)&g_kl[idx] = lp;
                    } else {               // Q, V: hi only
                        *(uint32_t*)&Oh[idx] = pack_f16(x0, x1);
                    }
                }
            }
        }
    }
}

// ---------------- flash attention: fp16, 2-pass QK, 1-pass PV ---------------
#define FQ 128
#define FK 64
#define FSTR 144
#define QH_OFF 0
#define KV_OFF 18432
#define KVST   27648            // per stage: kh, kl, vh (9216 each)
#define KL_O 9216
#define VH_O 18432
#define FLASH_SMEM 73728        // 72 KB -> 2 CTAs/SM

__device__ __forceinline__ void flash_load_kv(uint32_t sb, int j, int tid, size_t bh)
{
#pragma unroll
    for (int it = 0; it < 6; it++) {
        const int flat = it * 256 + tid;                 // 0..1535
        const int arr = flat / 512, rem = flat & 511;
        const int row = rem >> 3, seg = rem & 7;
        const __half* src = (arr == 0) ? g_kh : (arr == 1) ? g_kl : g_vh;
        cp16(sb + KV_OFF + (j & 1) * KVST + arr * 9216 + row * FSTR + seg * 16,
             src + (bh * Ssz + j * FK + row) * Dk + seg * 8);
    }
    cp_commit();
}

__global__ __launch_bounds__(256, 2)
void flash(const uint32_t* __restrict__ mb, __half* __restrict__ xh)
{
    extern __shared__ char smem[];
    const uint32_t sb = smem_u32(smem);
    const int tid = threadIdx.x, lane = tid & 31, w = tid >> 5;
    const int b = blockIdx.z, h = blockIdx.y, q0 = blockIdx.x * FQ;
    const size_t bh = (size_t)(b * Hh + h);
    const int grp = lane >> 2, qc = lane & 3;
    const int row_a = q0 + w * 16 + grp;

    flash_load_kv(sb, 0, tid, bh);
#pragma unroll
    for (int it = 0; it < 4; it++) {
        const int flat = it * 256 + tid;                 // 0..1023
        const int row = flat >> 3, seg = flat & 7;
        cp16(sb + QH_OFF + row * FSTR + seg * 16,
             g_qh + (bh * Ssz + q0 + row) * Dk + seg * 8);
    }
    cp_commit();
    cp_wait0();
    __syncthreads();

    // hoist loop-invariant Q-hi fragments
    const uint32_t qrow = (uint32_t)(w * 16 + ((lane >> 3) & 1) * 8 + (lane & 7)) * FSTR +
                          (lane >> 4) * 16;
    uint32_t qfh[4][4];
#pragma unroll
    for (int kt = 0; kt < 4; kt++) ldsm4(qfh[kt], sb + QH_OFF + qrow + kt * 32);

    float acc_o[8][4];
#pragma unroll
    for (int nt = 0; nt < 8; nt++)
#pragma unroll
        for (int r = 0; r < 4; r++) acc_o[nt][r] = 0.f;
    float m_a = -CUDART_INF_F, m_b = -CUDART_INF_F, l_a = 0.f, l_b = 0.f;

    const uint32_t* mrow_a = mb + ((size_t)b * Ssz + row_a) * (Ssz / 32);
    const uint32_t* mrow_b = mrow_a + 8 * (Ssz / 32);

    const int NJT = Ssz / FK;   // 32
    for (int jt = 0; jt < NJT; jt++) {
        const uint2 wa = *(const uint2*)(mrow_a + jt * 2);
        const uint2 wb = *(const uint2*)(mrow_b + jt * 2);
        if (jt > 0) { cp_wait0(); __syncthreads(); }
        if (jt + 1 < NJT) flash_load_kv(sb, jt + 1, tid, bh);
        const uint32_t st = sb + KV_OFF + (jt & 1) * KVST;

        // ---- QK^T: Qh·Kh + Qh·Kl (2-pass) ----
        float s[8][4];
#pragma unroll
        for (int nt = 0; nt < 8; nt++)
#pragma unroll
            for (int r = 0; r < 4; r++) s[nt][r] = 0.f;
#pragma unroll
        for (int kt = 0; kt < 4; kt++) {
#pragma unroll
            for (int hf = 0; hf < 2; hf++) {
                uint32_t b_h[2][4], b_l[2][4];
#pragma unroll
                for (int j = 0; j < 2; j++) {
                    const int nt2 = hf * 2 + j;
                    const uint32_t rb = st +
                        (uint32_t)(nt2 * 16 + (lane >> 4) * 8 + (lane & 7)) * FSTR +
                        kt * 32 + ((lane >> 3) & 1) * 16;
                    ldsm4(b_h[j], rb);
                    ldsm4(b_l[j], rb + KL_O);
                }
#pragma unroll
                for (int j = 0; j < 2; j++) {
                    mma16816(s[(hf * 2 + j) * 2],     qfh[kt], b_h[j]);
                    mma16816(s[(hf * 2 + j) * 2 + 1], qfh[kt], b_h[j] + 2);
                }
#pragma unroll
                for (int j = 0; j < 2; j++) {
                    mma16816(s[(hf * 2 + j) * 2],     qfh[kt], b_l[j]);
                    mma16816(s[(hf * 2 + j) * 2 + 1], qfh[kt], b_l[j] + 2);
                }
            }
        }

        // ---- scale + mask + online softmax (fp32 exp, fp32 sums) ----
        float ra = -CUDART_INF_F, rbx = -CUDART_INF_F;
#pragma unroll
        for (int nt = 0; nt < 8; nt++) {
            const int kk = nt * 8 + qc * 2;
            const uint32_t wA = (nt < 4) ? wa.x : wa.y;
            const uint32_t wB = (nt < 4) ? wb.x : wb.y;
            const int bit = kk & 31;
            s[nt][0] = ((wA >> bit) & 1)       ? s[nt][0] * 0.125f : -1e9f;
            s[nt][1] = ((wA >> (bit + 1)) & 1) ? s[nt][1] * 0.125f : -1e9f;
            s[nt][2] = ((wB >> bit) & 1)       ? s[nt][2] * 0.125f : -1e9f;
            s[nt][3] = ((wB >> (bit + 1)) & 1) ? s[nt][3] * 0.125f : -1e9f;
            ra  = fmaxf(ra,  fmaxf(s[nt][0], s[nt][1]));
            rbx = fmaxf(rbx, fmaxf(s[nt][2], s[nt][3]));
        }
        ra = qmax(ra); rbx = qmax(rbx);
        const float mna = fmaxf(m_a, ra), mnb = fmaxf(m_b, rbx);
        const float ca = __expf(m_a - mna), cb = __expf(m_b - mnb);
        float suma = 0.f, sumb = 0.f;
#pragma unroll
        for (int nt = 0; nt < 8; nt++) {
            s[nt][0] = __expf(s[nt][0] - mna);
            s[nt][1] = __expf(s[nt][1] - mna);
            s[nt][2] = __expf(s[nt][2] - mnb);
            s[nt][3] = __expf(s[nt][3] - mnb);
            suma += s[nt][0] + s[nt][1];
            sumb += s[nt][2] + s[nt][3];
        }
        l_a = l_a * ca + qsum(suma);
        l_b = l_b * cb + qsum(sumb);
#pragma unroll
        for (int nt = 0; nt < 8; nt++) {
            acc_o[nt][0] *= ca; acc_o[nt][1] *= ca;
            acc_o[nt][2] *= cb; acc_o[nt][3] *= cb;
        }
        m_a = mna; m_b = mnb;

        // ---- P @ V: single pass, P rounded to fp16 in registers ----
#pragma unroll
        for (int kt2 = 0; kt2 < 4; kt2++) {
            uint32_t p_h[4];
            p_h[0] = pack_f16(s[2 * kt2][0],     s[2 * kt2][1]);
            p_h[1] = pack_f16(s[2 * kt2][2],     s[2 * kt2][3]);
            p_h[2] = pack_f16(s[2 * kt2 + 1][0], s[2 * kt2 + 1][1]);
            p_h[3] = pack_f16(s[2 * kt2 + 1][2], s[2 * kt2 + 1][3]);
#pragma unroll
            for (int hf = 0; hf < 2; hf++) {
                uint32_t v_h[2][4];
#pragma unroll
                for (int j = 0; j < 2; j++) {
                    const int nd2 = hf * 2 + j;
                    const uint32_t vb = st + VH_O +
                        (uint32_t)(kt2 * 16 + ((lane >> 3) & 1) * 8 + (lane & 7)) * FSTR +
                        nd2 * 32 + (lane >> 4) * 16;
                    ldsm4t(v_h[j], vb);
                }
#pragma unroll
                for (int j = 0; j < 2; j++) {
                    mma16816(acc_o[(hf * 2 + j) * 2],     p_h, v_h[j]);
                    mma16816(acc_o[(hf * 2 + j) * 2 + 1], p_h, v_h[j] + 2);
                }
            }
        }
    }

    // epilogue: x hi-only fp16
    const float inva = 1.f / l_a, invb = 1.f / l_b;
#pragma unroll
    for (int nt = 0; nt < 8; nt++) {
        const int col = h * Dk + nt * 8 + qc * 2;
        size_t idx = ((size_t)b * Ssz + row_a) * Dm + col;
        *(uint32_t*)&xh[idx] = pack_f16(acc_o[nt][0] * inva, acc_o[nt][1] * inva);
        idx = ((size_t)b * Ssz + row_a + 8) * Dm + col;
        *(uint32_t*)&xh[idx] = pack_f16(acc_o[nt][2] * invb, acc_o[nt][3] * invb);
    }
}

// ---------------- launch ----------------------------------------------------
extern "C" void kernel_launch(void* const* d_in, const int* in_sizes, int n_in,
                              void* d_out, int out_size)
{
    (void)in_sizes; (void)n_in; (void)out_size;
    const float* query  = (const float*)d_in[0];
    const float* key_in = (const float*)d_in[1];
    const float* value  = (const float*)d_in[2];
    const int*   mask   = (const int*)  d_in[3];
    const float* Wq = (const float*)d_in[4];
    const float* bq = (const float*)d_in[5];
    const float* Wk = (const float*)d_in[6];
    const float* bk = (const float*)d_in[7];
    const float* Wv = (const float*)d_in[8];
    const float* bv = (const float*)d_in[9];
    const float* Wo = (const float*)d_in[10];
    const float* bo = (const float*)d_in[11];
    float* out = (float*)d_out;

    __half* ah;
    uint32_t* mbp;
    cudaGetSymbolAddress((void**)&ah, g_ah);
    cudaGetSymbolAddress((void**)&mbp, g_mb);

    cudaFuncSetAttribute(tgemm<0>, cudaFuncAttributeMaxDynamicSharedMemorySize, GEMM_SMEM);
    cudaFuncSetAttribute(tgemm<1>, cudaFuncAttributeMaxDynamicSharedMemorySize, GEMM_SMEM);
    cudaFuncSetAttribute(flash, cudaFuncAttributeMaxDynamicSharedMemorySize, FLASH_SMEM);

    // mask pack
    maskpack_kernel<<<(Bsz * Ssz * Ssz) / 256, 256>>>(mask, mbp);
    // fused conversions
    dim3 wgrid((Dm * Dm / 4) / 256, 1, 4);
    cvtW_kernel<<<wgrid, 256>>>(Wq, Wk, Wv, Wo);
    dim3 agrid((int)((MD / 4) / 256), 1, 3);
    cvtA_kernel<<<agrid, 256>>>(query, key_in, value);
    // fused Q/K/V projections (64x128 tiles, 128 threads)
    dim3 pgrid(Dm / 128, 8192 / 64, 3);
    tgemm<1><<<pgrid, 128, GEMM_SMEM>>>(bq, bk, bv, nullptr);
    // attention (x hi -> activation slot 0)
    dim3 fgrid(Ssz / FQ, Hh, Bsz);
    flash<<<fgrid, 256, FLASH_SMEM>>>(mbp, ah);
    // output projection
    dim3 ogrid(Dm / 128, 8192 / 64);
    tgemm<0><<<ogrid, 128, GEMM_SMEM>>>(bo, nullptr, nullptr, out);
}

// round 12
// speedup vs baseline: 1.1265x; 1.1026x over previous
#include <cuda_runtime.h>
#include <cuda_fp16.h>
#include <math_constants.h>
#include <cstdint>

#define Bsz 4
#define Ssz 2048
#define Dm  1024
#define Hh  16
#define Dk  64
#define BH  (Bsz * Hh)
#define MD  ((size_t)8192 * 1024)
#define DD  ((size_t)1024 * 1024)

// ---------------- scratch (device globals; no allocation allowed) ----------
__device__ __align__(1024) __half g_qh[MD];            // Q hi (head-split)
__device__ __align__(1024) __half g_kh[MD];            // K hi
__device__ __align__(1024) __half g_vh[MD];            // V hi
__device__ __align__(1024) __half g_ah[3 * MD];        // activations hi (q,k,v); slot0 reused for x
__device__ __align__(1024) __half g_wh[4 * DD];        // weights hi (Wq,Wk,Wv,Wo)
__device__ __align__(1024) __half g_wl[4 * DD];        // weights lo
__device__ __align__(1024) uint32_t g_mb[(size_t)Bsz * Ssz * (Ssz / 32)];

// ---------------- PTX helpers ----------------------------------------------
__device__ __forceinline__ uint32_t smem_u32(const void* p) {
    uint32_t a;
    asm("{ .reg .u64 t; cvta.to.shared.u64 t, %1; cvt.u32.u64 %0, t; }" : "=r"(a) : "l"(p));
    return a;
}
__device__ __forceinline__ void cp16(uint32_t dst, const void* src) {
    asm volatile("cp.async.cg.shared.global [%0], [%1], 16;" :: "r"(dst), "l"(src));
}
__device__ __forceinline__ void cp_commit() { asm volatile("cp.async.commit_group;"); }
__device__ __forceinline__ void cp_wait0()  { asm volatile("cp.async.wait_group 0;"); }

__device__ __forceinline__ void ldsm4(uint32_t* r, uint32_t a) {
    asm volatile("ldmatrix.sync.aligned.m8n8.x4.shared.b16 {%0,%1,%2,%3}, [%4];"
                 : "=r"(r[0]), "=r"(r[1]), "=r"(r[2]), "=r"(r[3]) : "r"(a));
}
__device__ __forceinline__ void ldsm4t(uint32_t* r, uint32_t a) {
    asm volatile("ldmatrix.sync.aligned.m8n8.x4.trans.shared.b16 {%0,%1,%2,%3}, [%4];"
                 : "=r"(r[0]), "=r"(r[1]), "=r"(r[2]), "=r"(r[3]) : "r"(a));
}
__device__ __forceinline__ void mma16816(float* d, const uint32_t* a, const uint32_t* b) {
    asm volatile("mma.sync.aligned.m16n8k16.row.col.f32.f16.f16.f32 "
                 "{%0,%1,%2,%3}, {%4,%5,%6,%7}, {%8,%9}, {%0,%1,%2,%3};"
                 : "+f"(d[0]), "+f"(d[1]), "+f"(d[2]), "+f"(d[3])
                 : "r"(a[0]), "r"(a[1]), "r"(a[2]), "r"(a[3]), "r"(b[0]), "r"(b[1]));
}
__device__ __forceinline__ uint32_t pack_f16(float lo, float hi) {
    uint32_t r;
    asm("cvt.rn.f16x2.f32 %0, %1, %2;" : "=r"(r) : "f"(hi), "f"(lo));
    return r;
}
__device__ __forceinline__ void split2(float v0, float v1, uint32_t& hp, uint32_t& lp) {
    hp = pack_f16(v0, v1);
    __half2 h2 = *reinterpret_cast<__half2*>(&hp);
    float r0 = v0 - __half2float(h2.x);
    float r1 = v1 - __half2float(h2.y);
    lp = pack_f16(r0, r1);
}
__device__ __forceinline__ float qmax(float v) {
    v = fmaxf(v, __shfl_xor_sync(0xffffffffu, v, 1));
    v = fmaxf(v, __shfl_xor_sync(0xffffffffu, v, 2));
    return v;
}
__device__ __forceinline__ float qsum(float v) {
    v += __shfl_xor_sync(0xffffffffu, v, 1);
    v += __shfl_xor_sync(0xffffffffu, v, 2);
    return v;
}

// ---------------- fused fp32 -> fp16 conversions ----------------------------
__global__ __launch_bounds__(256)
void cvtW_kernel(const float* __restrict__ w0, const float* __restrict__ w1,
                 const float* __restrict__ w2, const float* __restrict__ w3)
{
    const int z = blockIdx.z;
    const float* src = (z == 0) ? w0 : (z == 1) ? w1 : (z == 2) ? w2 : w3;
    __half* hi = g_wh + (size_t)z * DD;
    __half* lo = g_wl + (size_t)z * DD;
    const int i = blockIdx.x * 256 + threadIdx.x;
    float4 v = ((const float4*)src)[i];
    uint32_t h0, l0, h1, l1;
    split2(v.x, v.y, h0, l0);
    split2(v.z, v.w, h1, l1);
    ((uint2*)hi)[i] = make_uint2(h0, h1);
    ((uint2*)lo)[i] = make_uint2(l0, l1);
}

__global__ __launch_bounds__(256)
void cvtA_kernel(const float* __restrict__ a0, const float* __restrict__ a1,
                 const float* __restrict__ a2)
{
    const int z = blockIdx.z;
    const float* src = (z == 0) ? a0 : (z == 1) ? a1 : a2;
    __half* hi = g_ah + (size_t)z * MD;
    const int i = blockIdx.x * 256 + threadIdx.x;
    float4 v = ((const float4*)src)[i];
    ((uint2*)hi)[i] = make_uint2(pack_f16(v.x, v.y), pack_f16(v.z, v.w));
}

// ---------------- mask -> bitmask pack --------------------------------------
__global__ __launch_bounds__(256)
void maskpack_kernel(const int* __restrict__ mask, uint32_t* __restrict__ bits)
{
    const int i = blockIdx.x * 256 + threadIdx.x;
    const uint32_t b = __ballot_sync(0xffffffffu, mask[i] != 0);
    if ((threadIdx.x & 31) == 0) bits[i >> 5] = b;
}

// ---------------- tensor-core 2-pass fp16 GEMM (R9 config) ------------------
#define GSTRIDE 80
#define GARR    10240
#define GSTAGE  30720            // 3 arrays (Ah, Wh, Wl)
#define GEMM_SMEM (2 * GSTAGE)

__device__ __forceinline__ void gemm_load(uint32_t sb, int stage, int c, int tid,
                                          int m0, int n0,
                                          const __half* Ah, const __half* Wh, const __half* Wl)
{
#pragma unroll
    for (int it = 0; it < 6; it++) {
        const int flat = it * 256 + tid;                 // 0..1535
        const int arr = flat / 512, rem = flat & 511;
        const int row = rem >> 2, seg = rem & 3;
        const __half* src = (arr == 0) ? Ah : (arr == 1) ? Wh : Wl;
        const int gbase = (arr == 0) ? m0 : n0;
        cp16(sb + stage * GSTAGE + arr * GARR + row * GSTRIDE + seg * 16,
             src + (size_t)(gbase + row) * Dm + c * 32 + seg * 8);
    }
    cp_commit();
}

// MODE 0: output projection -> fp32 C.  MODE 1: per-z projection -> head-split fp16 hi.
template <int MODE>
__global__ __launch_bounds__(256, 2)
void tgemm(const float* __restrict__ b0p, const float* __restrict__ b1p,
           const float* __restrict__ b2p, float* __restrict__ C)
{
    extern __shared__ char smem[];
    const uint32_t sb = smem_u32(smem);
    const int tid = threadIdx.x;
    const int lane = tid & 31, w = tid >> 5;
    const int wm = w >> 1, wn = w & 1;
    const int m0 = blockIdx.y * 128, n0 = blockIdx.x * 128;
    const int z = (MODE == 1) ? blockIdx.z : 3;

    const __half* Ah = g_ah + ((MODE == 1) ? (size_t)z * MD : 0);
    const __half* Wh = g_wh + (size_t)z * DD;
    const __half* Wl = g_wl + (size_t)z * DD;
    const float* bias = (MODE == 0) ? b0p : (z == 0) ? b0p : (z == 1) ? b1p : b2p;
    __half* Oh = (MODE == 1) ? ((z == 0) ? g_qh : (z == 1) ? g_kh : g_vh) : nullptr;

    float acc[2][8][4];
#pragma unroll
    for (int mt = 0; mt < 2; mt++)
#pragma unroll
        for (int nt = 0; nt < 8; nt++)
#pragma unroll
            for (int r = 0; r < 4; r++) acc[mt][nt][r] = 0.f;

    gemm_load(sb, 0, 0, tid, m0, n0, Ah, Wh, Wl);

    for (int c = 0; c < 32; c++) {
        cp_wait0();
        __syncthreads();
        if (c + 1 < 32) gemm_load(sb, (c + 1) & 1, c + 1, tid, m0, n0, Ah, Wh, Wl);
        const uint32_t st = sb + (c & 1) * GSTAGE;
#pragma unroll
        for (int kt = 0; kt < 2; kt++) {
            uint32_t a_h[2][4];
#pragma unroll
            for (int mt = 0; mt < 2; mt++) {
                const uint32_t ra = st +
                    (uint32_t)(wm * 32 + mt * 16 + ((lane >> 3) & 1) * 8 + (lane & 7)) * GSTRIDE +
                    kt * 32 + (lane >> 4) * 16;
                ldsm4(a_h[mt], ra);
            }
#pragma unroll
            for (int hf = 0; hf < 2; hf++) {
                uint32_t b_h[2][4], b_l[2][4];
#pragma unroll
                for (int j = 0; j < 2; j++) {
                    const int nt2 = hf * 2 + j;
                    const uint32_t rb = st + GARR +
                        (uint32_t)(wn * 64 + nt2 * 16 + (lane >> 4) * 8 + (lane & 7)) * GSTRIDE +
                        kt * 32 + ((lane >> 3) & 1) * 16;
                    ldsm4(b_h[j], rb);
                    ldsm4(b_l[j], rb + GARR);
                }
#pragma unroll
                for (int mt = 0; mt < 2; mt++)
#pragma unroll
                    for (int j = 0; j < 2; j++) {
                        mma16816(acc[mt][(hf * 2 + j) * 2],     a_h[mt], b_h[j]);
                        mma16816(acc[mt][(hf * 2 + j) * 2 + 1], a_h[mt], b_h[j] + 2);
                    }
#pragma unroll
                for (int mt = 0; mt < 2; mt++)
#pragma unroll
                    for (int j = 0; j < 2; j++) {
                        mma16816(acc[mt][(hf * 2 + j) * 2],     a_h[mt], b_l[j]);
                        mma16816(acc[mt][(hf * 2 + j) * 2 + 1], a_h[mt], b_l[j] + 2);
                    }
            }
        }
    }

    const int grp = lane >> 2, qc = lane & 3;
#pragma unroll
    for (int mt = 0; mt < 2; mt++) {
#pragma unroll
        for (int nt = 0; nt < 8; nt++) {
            const int row = m0 + wm * 32 + mt * 16 + grp;
            const int col = n0 + wn * 64 + nt * 8 + qc * 2;
            const float b0 = bias[col], b1 = bias[col + 1];
            const float v0 = acc[mt][nt][0] + b0, v1 = acc[mt][nt][1] + b1;
            const float v2 = acc[mt][nt][2] + b0, v3 = acc[mt][nt][3] + b1;
            if (MODE == 0) {
                *(float2*)&C[(size_t)row * Dm + col]       = make_float2(v0, v1);
                *(float2*)&C[(size_t)(row + 8) * Dm + col] = make_float2(v2, v3);
            } else {
                const int hh = col >> 6, dk = col & 63;
#pragma unroll
                for (int half_i = 0; half_i < 2; half_i++) {
                    const int r2 = row + half_i * 8;
                    const int bb = r2 >> 11, s = r2 & 2047;
                    const size_t idx = (((size_t)(bb * Hh + hh)) * Ssz + s) * Dk + dk;
                    const float x0 = half_i ? v2 : v0, x1 = half_i ? v3 : v1;
                    *(uint32_t*)&Oh[idx] = pack_f16(x0, x1);
                }
            }
        }
    }
}

// ---------------- flash attention: fp16, 1-pass QK, 1-pass PV ---------------
#define FQ 128
#define FK 64
#define FSTR 144
#define QH_OFF 0
#define KV_OFF 18432
#define KVST   18432            // per stage: kh, vh (9216 each)
#define VH_O 9216
#define FLASH_SMEM 55296        // 54 KB -> 2 CTAs/SM (regs bound anyway)

__device__ __forceinline__ void flash_load_kv(uint32_t sb, int j, int tid, size_t bh)
{
#pragma unroll
    for (int it = 0; it < 4; it++) {
        const int flat = it * 256 + tid;                 // 0..1023
        const int arr = flat >> 9, rem = flat & 511;     // 0: kh, 1: vh
        const int row = rem >> 3, seg = rem & 7;
        const __half* src = (arr == 0) ? g_kh : g_vh;
        cp16(sb + KV_OFF + (j & 1) * KVST + arr * 9216 + row * FSTR + seg * 16,
             src + (bh * Ssz + j * FK + row) * Dk + seg * 8);
    }
    cp_commit();
}

__global__ __launch_bounds__(256, 2)
void flash(const uint32_t* __restrict__ mb, __half* __restrict__ xh)
{
    extern __shared__ char smem[];
    const uint32_t sb = smem_u32(smem);
    const int tid = threadIdx.x, lane = tid & 31, w = tid >> 5;
    const int b = blockIdx.z, h = blockIdx.y, q0 = blockIdx.x * FQ;
    const size_t bh = (size_t)(b * Hh + h);
    const int grp = lane >> 2, qc = lane & 3;
    const int row_a = q0 + w * 16 + grp;

    flash_load_kv(sb, 0, tid, bh);
#pragma unroll
    for (int it = 0; it < 4; it++) {
        const int flat = it * 256 + tid;                 // 0..1023
        const int row = flat >> 3, seg = flat & 7;
        cp16(sb + QH_OFF + row * FSTR + seg * 16,
             g_qh + (bh * Ssz + q0 + row) * Dk + seg * 8);
    }
    cp_commit();
    cp_wait0();
    __syncthreads();

    // hoist loop-invariant Q-hi fragments
    const uint32_t qrow = (uint32_t)(w * 16 + ((lane >> 3) & 1) * 8 + (lane & 7)) * FSTR +
                          (lane >> 4) * 16;
    uint32_t qfh[4][4];
#pragma unroll
    for (int kt = 0; kt < 4; kt++) ldsm4(qfh[kt], sb + QH_OFF + qrow + kt * 32);

    float acc_o[8][4];
#pragma unroll
    for (int nt = 0; nt < 8; nt++)
#pragma unroll
        for (int r = 0; r < 4; r++) acc_o[nt][r] = 0.f;
    float m_a = -CUDART_INF_F, m_b = -CUDART_INF_F, l_a = 0.f, l_b = 0.f;

    const uint32_t* mrow_a = mb + ((size_t)b * Ssz + row_a) * (Ssz / 32);
    const uint32_t* mrow_b = mrow_a + 8 * (Ssz / 32);

    const int NJT = Ssz / FK;   // 32
    for (int jt = 0; jt < NJT; jt++) {
        const uint2 wa = *(const uint2*)(mrow_a + jt * 2);
        const uint2 wb = *(const uint2*)(mrow_b + jt * 2);
        if (jt > 0) { cp_wait0(); __syncthreads(); }
        if (jt + 1 < NJT) flash_load_kv(sb, jt + 1, tid, bh);
        const uint32_t st = sb + KV_OFF + (jt & 1) * KVST;

        // ---- QK^T: Qh·Kh (single pass) ----
        float s[8][4];
#pragma unroll
        for (int nt = 0; nt < 8; nt++)
#pragma unroll
            for (int r = 0; r < 4; r++) s[nt][r] = 0.f;
#pragma unroll
        for (int kt = 0; kt < 4; kt++) {
#pragma unroll
            for (int hf = 0; hf < 2; hf++) {
                uint32_t b_h[2][4];
#pragma unroll
                for (int j = 0; j < 2; j++) {
                    const int nt2 = hf * 2 + j;
                    const uint32_t rb = st +
                        (uint32_t)(nt2 * 16 + (lane >> 4) * 8 + (lane & 7)) * FSTR +
                        kt * 32 + ((lane >> 3) & 1) * 16;
                    ldsm4(b_h[j], rb);
                }
#pragma unroll
                for (int j = 0; j < 2; j++) {
                    mma16816(s[(hf * 2 + j) * 2],     qfh[kt], b_h[j]);
                    mma16816(s[(hf * 2 + j) * 2 + 1], qfh[kt], b_h[j] + 2);
                }
            }
        }

        // ---- scale + mask + online softmax (fp32 exp, fp32 sums) ----
        float ra = -CUDART_INF_F, rbx = -CUDART_INF_F;
#pragma unroll
        for (int nt = 0; nt < 8; nt++) {
            const int kk = nt * 8 + qc * 2;
            const uint32_t wA = (nt < 4) ? wa.x : wa.y;
            const uint32_t wB = (nt < 4) ? wb.x : wb.y;
            const int bit = kk & 31;
            s[nt][0] = ((wA >> bit) & 1)       ? s[nt][0] * 0.125f : -1e9f;
            s[nt][1] = ((wA >> (bit + 1)) & 1) ? s[nt][1] * 0.125f : -1e9f;
            s[nt][2] = ((wB >> bit) & 1)       ? s[nt][2] * 0.125f : -1e9f;
            s[nt][3] = ((wB >> (bit + 1)) & 1) ? s[nt][3] * 0.125f : -1e9f;
            ra  = fmaxf(ra,  fmaxf(s[nt][0], s[nt][1]));
            rbx = fmaxf(rbx, fmaxf(s[nt][2], s[nt][3]));
        }
        ra = qmax(ra); rbx = qmax(rbx);
        const float mna = fmaxf(m_a, ra), mnb = fmaxf(m_b, rbx);
        const float ca = __expf(m_a - mna), cb = __expf(m_b - mnb);
        float suma = 0.f, sumb = 0.f;
#pragma unroll
        for (int nt = 0; nt < 8; nt++) {
            s[nt][0] = __expf(s[nt][0] - mna);
            s[nt][1] = __expf(s[nt][1] - mna);
            s[nt][2] = __expf(s[nt][2] - mnb);
            s[nt][3] = __expf(s[nt][3] - mnb);
            suma += s[nt][0] + s[nt][1];
            sumb += s[nt][2] + s[nt][3];
        }
        l_a = l_a * ca + qsum(suma);
        l_b = l_b * cb + qsum(sumb);
#pragma unroll
        for (int nt = 0; nt < 8; nt++) {
            acc_o[nt][0] *= ca; acc_o[nt][1] *= ca;
            acc_o[nt][2] *= cb; acc_o[nt][3] *= cb;
        }
        m_a = mna; m_b = mnb;

        // ---- P @ V: single pass, P rounded to fp16 in registers ----
#pragma unroll
        for (int kt2 = 0; kt2 < 4; kt2++) {
            uint32_t p_h[4];
            p_h[0] = pack_f16(s[2 * kt2][0],     s[2 * kt2][1]);
            p_h[1] = pack_f16(s[2 * kt2][2],     s[2 * kt2][3]);
            p_h[2] = pack_f16(s[2 * kt2 + 1][0], s[2 * kt2 + 1][1]);
            p_h[3] = pack_f16(s[2 * kt2 + 1][2], s[2 * kt2 + 1][3]);
#pragma unroll
            for (int hf = 0; hf < 2; hf++) {
                uint32_t v_h[2][4];
#pragma unroll
                for (int j = 0; j < 2; j++) {
                    const int nd2 = hf * 2 + j;
                    const uint32_t vb = st + VH_O +
                        (uint32_t)(kt2 * 16 + ((lane >> 3) & 1) * 8 + (lane & 7)) * FSTR +
                        nd2 * 32 + (lane >> 4) * 16;
                    ldsm4t(v_h[j], vb);
                }
#pragma unroll
                for (int j = 0; j < 2; j++) {
                    mma16816(acc_o[(hf * 2 + j) * 2],     p_h, v_h[j]);
                    mma16816(acc_o[(hf * 2 + j) * 2 + 1], p_h, v_h[j] + 2);
                }
            }
        }
    }

    // epilogue: x hi-only fp16
    const float inva = 1.f / l_a, invb = 1.f / l_b;
#pragma unroll
    for (int nt = 0; nt < 8; nt++) {
        const int col = h * Dk + nt * 8 + qc * 2;
        size_t idx = ((size_t)b * Ssz + row_a) * Dm + col;
        *(uint32_t*)&xh[idx] = pack_f16(acc_o[nt][0] * inva, acc_o[nt][1] * inva);
        idx = ((size_t)b * Ssz + row_a + 8) * Dm + col;
        *(uint32_t*)&xh[idx] = pack_f16(acc_o[nt][2] * invb, acc_o[nt][3] * invb);
    }
}

// ---------------- launch ----------------------------------------------------
extern "C" void kernel_launch(void* const* d_in, const int* in_sizes, int n_in,
                              void* d_out, int out_size)
{
    (void)in_sizes; (void)n_in; (void)out_size;
    const float* query  = (const float*)d_in[0];
    const float* key_in = (const float*)d_in[1];
    const float* value  = (const float*)d_in[2];
    const int*   mask   = (const int*)  d_in[3];
    const float* Wq = (const float*)d_in[4];
    const float* bq = (const float*)d_in[5];
    const float* Wk = (const float*)d_in[6];
    const float* bk = (const float*)d_in[7];
    const float* Wv = (const float*)d_in[8];
    const float* bv = (const float*)d_in[9];
    const float* Wo = (const float*)d_in[10];
    const float* bo = (const float*)d_in[11];
    float* out = (float*)d_out;

    __half* ah;
    uint32_t* mbp;
    cudaGetSymbolAddress((void**)&ah, g_ah);
    cudaGetSymbolAddress((void**)&mbp, g_mb);

    cudaFuncSetAttribute(tgemm<0>, cudaFuncAttributeMaxDynamicSharedMemorySize, GEMM_SMEM);
    cudaFuncSetAttribute(tgemm<1>, cudaFuncAttributeMaxDynamicSharedMemorySize, GEMM_SMEM);
    cudaFuncSetAttribute(flash, cudaFuncAttributeMaxDynamicSharedMemorySize, FLASH_SMEM);

    // mask pack
    maskpack_kernel<<<(Bsz * Ssz * Ssz) / 256, 256>>>(mask, mbp);
    // fused conversions
    dim3 wgrid((Dm * Dm / 4) / 256, 1, 4);
    cvtW_kernel<<<wgrid, 256>>>(Wq, Wk, Wv, Wo);
    dim3 agrid((int)((MD / 4) / 256), 1, 3);
    cvtA_kernel<<<agrid, 256>>>(query, key_in, value);
    // fused Q/K/V projections
    dim3 pgrid(Dm / 128, 8192 / 128, 3);
    tgemm<1><<<pgrid, 256, GEMM_SMEM>>>(bq, bk, bv, nullptr);
    // attention (x hi -> activation slot 0)
    dim3 fgrid(Ssz / FQ, Hh, Bsz);
    flash<<<fgrid, 256, FLASH_SMEM>>>(mbp, ah);
    // output projection
    dim3 ogrid(Dm / 128, 8192 / 128);
    tgemm<0><<<ogrid, 256, GEMM_SMEM>>>(bo, nullptr, nullptr, out);
}

// round 13
// speedup vs baseline: 1.4662x; 1.3016x over previous
#include <cuda_runtime.h>
#include <cuda_fp16.h>
#include <math_constants.h>
#include <cstdint>

#define Bsz 4
#define Ssz 2048
#define Dm  1024
#define Hh  16
#define Dk  64
#define BH  (Bsz * Hh)
#define MD  ((size_t)8192 * 1024)
#define DD  ((size_t)1024 * 1024)

// ---------------- scratch (device globals; no allocation allowed) ----------
__device__ __align__(1024) __half g_qh[MD];            // Q hi (head-split)
__device__ __align__(1024) __half g_kh[MD];            // K hi
__device__ __align__(1024) __half g_vh[MD];            // V hi
__device__ __align__(1024) __half g_ah[3 * MD];        // activations hi (q,k,v); slot0 reused for x
__device__ __align__(1024) __half g_wh[4 * DD];        // weights hi (Wq,Wk,Wv,Wo)
__device__ __align__(1024) uint32_t g_mb[(size_t)Bsz * Ssz * (Ssz / 32)];

// ---------------- PTX helpers ----------------------------------------------
__device__ __forceinline__ uint32_t smem_u32(const void* p) {
    uint32_t a;
    asm("{ .reg .u64 t; cvta.to.shared.u64 t, %1; cvt.u32.u64 %0, t; }" : "=r"(a) : "l"(p));
    return a;
}
__device__ __forceinline__ void cp16(uint32_t dst, const void* src) {
    asm volatile("cp.async.cg.shared.global [%0], [%1], 16;" :: "r"(dst), "l"(src));
}
__device__ __forceinline__ void cp_commit() { asm volatile("cp.async.commit_group;"); }
__device__ __forceinline__ void cp_wait0()  { asm volatile("cp.async.wait_group 0;"); }

__device__ __forceinline__ void ldsm4(uint32_t* r, uint32_t a) {
    asm volatile("ldmatrix.sync.aligned.m8n8.x4.shared.b16 {%0,%1,%2,%3}, [%4];"
                 : "=r"(r[0]), "=r"(r[1]), "=r"(r[2]), "=r"(r[3]) : "r"(a));
}
__device__ __forceinline__ void ldsm4t(uint32_t* r, uint32_t a) {
    asm volatile("ldmatrix.sync.aligned.m8n8.x4.trans.shared.b16 {%0,%1,%2,%3}, [%4];"
                 : "=r"(r[0]), "=r"(r[1]), "=r"(r[2]), "=r"(r[3]) : "r"(a));
}
__device__ __forceinline__ void mma16816(float* d, const uint32_t* a, const uint32_t* b) {
    asm volatile("mma.sync.aligned.m16n8k16.row.col.f32.f16.f16.f32 "
                 "{%0,%1,%2,%3}, {%4,%5,%6,%7}, {%8,%9}, {%0,%1,%2,%3};"
                 : "+f"(d[0]), "+f"(d[1]), "+f"(d[2]), "+f"(d[3])
                 : "r"(a[0]), "r"(a[1]), "r"(a[2]), "r"(a[3]), "r"(b[0]), "r"(b[1]));
}
__device__ __forceinline__ uint32_t pack_f16(float lo, float hi) {
    uint32_t r;
    asm("cvt.rn.f16x2.f32 %0, %1, %2;" : "=r"(r) : "f"(hi), "f"(lo));
    return r;
}
__device__ __forceinline__ float qmax(float v) {
    v = fmaxf(v, __shfl_xor_sync(0xffffffffu, v, 1));
    v = fmaxf(v, __shfl_xor_sync(0xffffffffu, v, 2));
    return v;
}
__device__ __forceinline__ float qsum(float v) {
    v += __shfl_xor_sync(0xffffffffu, v, 1);
    v += __shfl_xor_sync(0xffffffffu, v, 2);
    return v;
}

// ---------------- fused fp32 -> fp16 conversions ----------------------------
__global__ __launch_bounds__(256)
void cvtW_kernel(const float* __restrict__ w0, const float* __restrict__ w1,
                 const float* __restrict__ w2, const float* __restrict__ w3)
{
    const int z = blockIdx.z;
    const float* src = (z == 0) ? w0 : (z == 1) ? w1 : (z == 2) ? w2 : w3;
    __half* hi = g_wh + (size_t)z * DD;
    const int i = blockIdx.x * 256 + threadIdx.x;
    float4 v = ((const float4*)src)[i];
    ((uint2*)hi)[i] = make_uint2(pack_f16(v.x, v.y), pack_f16(v.z, v.w));
}

__global__ __launch_bounds__(256)
void cvtA_kernel(const float* __restrict__ a0, const float* __restrict__ a1,
                 const float* __restrict__ a2)
{
    const int z = blockIdx.z;
    const float* src = (z == 0) ? a0 : (z == 1) ? a1 : a2;
    __half* hi = g_ah + (size_t)z * MD;
    const int i = blockIdx.x * 256 + threadIdx.x;
    float4 v = ((const float4*)src)[i];
    ((uint2*)hi)[i] = make_uint2(pack_f16(v.x, v.y), pack_f16(v.z, v.w));
}

// ---------------- mask -> bitmask pack --------------------------------------
__global__ __launch_bounds__(256)
void maskpack_kernel(const int* __restrict__ mask, uint32_t* __restrict__ bits)
{
    const int i = blockIdx.x * 256 + threadIdx.x;
    const uint32_t b = __ballot_sync(0xffffffffu, mask[i] != 0);
    if ((threadIdx.x & 31) == 0) bits[i >> 5] = b;
}

// ---------------- tensor-core 1-pass fp16 GEMM ------------------------------
// C = Ah · Wh^T + bias; 128x128 CTA tile, BK=32, 2-stage, 2 CTAs/SM.
#define GSTRIDE 80
#define GARR    10240
#define GSTAGE  20480            // 2 arrays (Ah, Wh)
#define GEMM_SMEM (2 * GSTAGE)

__device__ __forceinline__ void gemm_load(uint32_t sb, int stage, int c, int tid,
                                          int m0, int n0,
                                          const __half* Ah, const __half* Wh)
{
#pragma unroll
    for (int it = 0; it < 4; it++) {
        const int flat = it * 256 + tid;                 // 0..1023
        const int arr = flat >> 9, rem = flat & 511;
        const int row = rem >> 2, seg = rem & 3;
        const __half* src = (arr == 0) ? Ah : Wh;
        const int gbase = (arr == 0) ? m0 : n0;
        cp16(sb + stage * GSTAGE + arr * GARR + row * GSTRIDE + seg * 16,
             src + (size_t)(gbase + row) * Dm + c * 32 + seg * 8);
    }
    cp_commit();
}

// MODE 0: output projection -> fp32 C.  MODE 1: per-z projection -> head-split fp16 hi.
template <int MODE>
__global__ __launch_bounds__(256, 2)
void tgemm(const float* __restrict__ b0p, const float* __restrict__ b1p,
           const float* __restrict__ b2p, float* __restrict__ C)
{
    extern __shared__ char smem[];
    const uint32_t sb = smem_u32(smem);
    const int tid = threadIdx.x;
    const int lane = tid & 31, w = tid >> 5;
    const int wm = w >> 1, wn = w & 1;
    const int m0 = blockIdx.y * 128, n0 = blockIdx.x * 128;
    const int z = (MODE == 1) ? blockIdx.z : 3;

    const __half* Ah = g_ah + ((MODE == 1) ? (size_t)z * MD : 0);
    const __half* Wh = g_wh + (size_t)z * DD;
    const float* bias = (MODE == 0) ? b0p : (z == 0) ? b0p : (z == 1) ? b1p : b2p;
    __half* Oh = (MODE == 1) ? ((z == 0) ? g_qh : (z == 1) ? g_kh : g_vh) : nullptr;

    float acc[2][8][4];
#pragma unroll
    for (int mt = 0; mt < 2; mt++)
#pragma unroll
        for (int nt = 0; nt < 8; nt++)
#pragma unroll
            for (int r = 0; r < 4; r++) acc[mt][nt][r] = 0.f;

    gemm_load(sb, 0, 0, tid, m0, n0, Ah, Wh);

    for (int c = 0; c < 32; c++) {
        cp_wait0();
        __syncthreads();
        if (c + 1 < 32) gemm_load(sb, (c + 1) & 1, c + 1, tid, m0, n0, Ah, Wh);
        const uint32_t st = sb + (c & 1) * GSTAGE;
#pragma unroll
        for (int kt = 0; kt < 2; kt++) {
            uint32_t a_h[2][4];
#pragma unroll
            for (int mt = 0; mt < 2; mt++) {
                const uint32_t ra = st +
                    (uint32_t)(wm * 32 + mt * 16 + ((lane >> 3) & 1) * 8 + (lane & 7)) * GSTRIDE +
                    kt * 32 + (lane >> 4) * 16;
                ldsm4(a_h[mt], ra);
            }
#pragma unroll
            for (int hf = 0; hf < 2; hf++) {
                uint32_t b_h[2][4];
#pragma unroll
                for (int j = 0; j < 2; j++) {
                    const int nt2 = hf * 2 + j;
                    const uint32_t rb = st + GARR +
                        (uint32_t)(wn * 64 + nt2 * 16 + (lane >> 4) * 8 + (lane & 7)) * GSTRIDE +
                        kt * 32 + ((lane >> 3) & 1) * 16;
                    ldsm4(b_h[j], rb);
                }
#pragma unroll
                for (int mt = 0; mt < 2; mt++)
#pragma unroll
                    for (int j = 0; j < 2; j++) {
                        mma16816(acc[mt][(hf * 2 + j) * 2],     a_h[mt], b_h[j]);
                        mma16816(acc[mt][(hf * 2 + j) * 2 + 1], a_h[mt], b_h[j] + 2);
                    }
            }
        }
    }

    const int grp = lane >> 2, qc = lane & 3;
#pragma unroll
    for (int mt = 0; mt < 2; mt++) {
#pragma unroll
        for (int nt = 0; nt < 8; nt++) {
            const int row = m0 + wm * 32 + mt * 16 + grp;
            const int col = n0 + wn * 64 + nt * 8 + qc * 2;
            const float b0 = bias[col], b1 = bias[col + 1];
            const float v0 = acc[mt][nt][0] + b0, v1 = acc[mt][nt][1] + b1;
            const float v2 = acc[mt][nt][2] + b0, v3 = acc[mt][nt][3] + b1;
            if (MODE == 0) {
                *(float2*)&C[(size_t)row * Dm + col]       = make_float2(v0, v1);
                *(float2*)&C[(size_t)(row + 8) * Dm + col] = make_float2(v2, v3);
            } else {
                const int hh = col >> 6, dk = col & 63;
#pragma unroll
                for (int half_i = 0; half_i < 2; half_i++) {
                    const int r2 = row + half_i * 8;
                    const int bb = r2 >> 11, s = r2 & 2047;
                    const size_t idx = (((size_t)(bb * Hh + hh)) * Ssz + s) * Dk + dk;
                    const float x0 = half_i ? v2 : v0, x1 = half_i ? v3 : v1;
                    *(uint32_t*)&Oh[idx] = pack_f16(x0, x1);
                }
            }
        }
    }
}

// ---------------- flash attention: fp16, 1-pass QK, 1-pass PV ---------------
#define FQ 128
#define FK 64
#define FSTR 144
#define QH_OFF 0
#define KV_OFF 18432
#define KVST   18432            // per stage: kh, vh (9216 each)
#define VH_O 9216
#define FLASH_SMEM 55296        // 54 KB -> 2 CTAs/SM

__device__ __forceinline__ void flash_load_kv(uint32_t sb, int j, int tid, size_t bh)
{
#pragma unroll
    for (int it = 0; it < 4; it++) {
        const int flat = it * 256 + tid;                 // 0..1023
        const int arr = flat >> 9, rem = flat & 511;     // 0: kh, 1: vh
        const int row = rem >> 3, seg = rem & 7;
        const __half* src = (arr == 0) ? g_kh : g_vh;
        cp16(sb + KV_OFF + (j & 1) * KVST + arr * 9216 + row * FSTR + seg * 16,
             src + (bh * Ssz + j * FK + row) * Dk + seg * 8);
    }
    cp_commit();
}

__global__ __launch_bounds__(256, 2)
void flash(const uint32_t* __restrict__ mb, __half* __restrict__ xh)
{
    extern __shared__ char smem[];
    const uint32_t sb = smem_u32(smem);
    const int tid = threadIdx.x, lane = tid & 31, w = tid >> 5;
    const int b = blockIdx.z, h = blockIdx.y, q0 = blockIdx.x * FQ;
    const size_t bh = (size_t)(b * Hh + h);
    const int grp = lane >> 2, qc = lane & 3;
    const int row_a = q0 + w * 16 + grp;

    flash_load_kv(sb, 0, tid, bh);
#pragma unroll
    for (int it = 0; it < 4; it++) {
        const int flat = it * 256 + tid;                 // 0..1023
        const int row = flat >> 3, seg = flat & 7;
        cp16(sb + QH_OFF + row * FSTR + seg * 16,
             g_qh + (bh * Ssz + q0 + row) * Dk + seg * 8);
    }
    cp_commit();
    cp_wait0();
    __syncthreads();

    // hoist loop-invariant Q-hi fragments
    const uint32_t qrow = (uint32_t)(w * 16 + ((lane >> 3) & 1) * 8 + (lane & 7)) * FSTR +
                          (lane >> 4) * 16;
    uint32_t qfh[4][4];
#pragma unroll
    for (int kt = 0; kt < 4; kt++) ldsm4(qfh[kt], sb + QH_OFF + qrow + kt * 32);

    float acc_o[8][4];
#pragma unroll
    for (int nt = 0; nt < 8; nt++)
#pragma unroll
        for (int r = 0; r < 4; r++) acc_o[nt][r] = 0.f;
    float m_a = -CUDART_INF_F, m_b = -CUDART_INF_F, l_a = 0.f, l_b = 0.f;

    const uint32_t* mrow_a = mb + ((size_t)b * Ssz + row_a) * (Ssz / 32);
    const uint32_t* mrow_b = mrow_a + 8 * (Ssz / 32);

    const int NJT = Ssz / FK;   // 32
    for (int jt = 0; jt < NJT; jt++) {
        const uint2 wa = *(const uint2*)(mrow_a + jt * 2);
        const uint2 wb = *(const uint2*)(mrow_b + jt * 2);
        if (jt > 0) { cp_wait0(); __syncthreads(); }
        if (jt + 1 < NJT) flash_load_kv(sb, jt + 1, tid, bh);
        const uint32_t st = sb + KV_OFF + (jt & 1) * KVST;

        // ---- QK^T: Qh·Kh (single pass) ----
        float s[8][4];
#pragma unroll
        for (int nt = 0; nt < 8; nt++)
#pragma unroll
            for (int r = 0; r < 4; r++) s[nt][r] = 0.f;
#pragma unroll
        for (int kt = 0; kt < 4; kt++) {
#pragma unroll
            for (int hf = 0; hf < 2; hf++) {
                uint32_t b_h[2][4];
#pragma unroll
                for (int j = 0; j < 2; j++) {
                    const int nt2 = hf * 2 + j;
                    const uint32_t rb = st +
                        (uint32_t)(nt2 * 16 + (lane >> 4) * 8 + (lane & 7)) * FSTR +
                        kt * 32 + ((lane >> 3) & 1) * 16;
                    ldsm4(b_h[j], rb);
                }
#pragma unroll
                for (int j = 0; j < 2; j++) {
                    mma16816(s[(hf * 2 + j) * 2],     qfh[kt], b_h[j]);
                    mma16816(s[(hf * 2 + j) * 2 + 1], qfh[kt], b_h[j] + 2);
                }
            }
        }

        // ---- scale + mask + online softmax (fp32 exp, fp32 sums) ----
        float ra = -CUDART_INF_F, rbx = -CUDART_INF_F;
#pragma unroll
        for (int nt = 0; nt < 8; nt++) {
            const int kk = nt * 8 + qc * 2;
            const uint32_t wA = (nt < 4) ? wa.x : wa.y;
            const uint32_t wB = (nt < 4) ? wb.x : wb.y;
            const int bit = kk & 31;
            s[nt][0] = ((wA >> bit) & 1)       ? s[nt][0] * 0.125f : -1e9f;
            s[nt][1] = ((wA >> (bit + 1)) & 1) ? s[nt][1] * 0.125f : -1e9f;
            s[nt][2] = ((wB >> bit) & 1)       ? s[nt][2] * 0.125f : -1e9f;
            s[nt][3] = ((wB >> (bit + 1)) & 1) ? s[nt][3] * 0.125f : -1e9f;
            ra  = fmaxf(ra,  fmaxf(s[nt][0], s[nt][1]));
            rbx = fmaxf(rbx, fmaxf(s[nt][2], s[nt][3]));
        }
        ra = qmax(ra); rbx = qmax(rbx);
        const float mna = fmaxf(m_a, ra), mnb = fmaxf(m_b, rbx);
        const float ca = __expf(m_a - mna), cb = __expf(m_b - mnb);
        float suma = 0.f, sumb = 0.f;
#pragma unroll
        for (int nt = 0; nt < 8; nt++) {
            s[nt][0] = __expf(s[nt][0] - mna);
            s[nt][1] = __expf(s[nt][1] - mna);
            s[nt][2] = __expf(s[nt][2] - mnb);
            s[nt][3] = __expf(s[nt][3] - mnb);
            suma += s[nt][0] + s[nt][1];
            sumb += s[nt][2] + s[nt][3];
        }
        l_a = l_a * ca + qsum(suma);
        l_b = l_b * cb + qsum(sumb);
#pragma unroll
        for (int nt = 0; nt < 8; nt++) {
            acc_o[nt][0] *= ca; acc_o[nt][1] *= ca;
            acc_o[nt][2] *= cb; acc_o[nt][3] *= cb;
        }
        m_a = mna; m_b = mnb;

        // ---- P @ V: single pass, P rounded to fp16 in registers ----
#pragma unroll
        for (int kt2 = 0; kt2 < 4; kt2++) {
            uint32_t p_h[4];
            p_h[0] = pack_f16(s[2 * kt2][0],     s[2 * kt2][1]);
            p_h[1] = pack_f16(s[2 * kt2][2],     s[2 * kt2][3]);
            p_h[2] = pack_f16(s[2 * kt2 + 1][0], s[2 * kt2 + 1][1]);
            p_h[3] = pack_f16(s[2 * kt2 + 1][2], s[2 * kt2 + 1][3]);
#pragma unroll
            for (int hf = 0; hf < 2; hf++) {
                uint32_t v_h[2][4];
#pragma unroll
                for (int j = 0; j < 2; j++) {
                    const int nd2 = hf * 2 + j;
                    const uint32_t vb = st + VH_O +
                        (uint32_t)(kt2 * 16 + ((lane >> 3) & 1) * 8 + (lane & 7)) * FSTR +
                        nd2 * 32 + (lane >> 4) * 16;
                    ldsm4t(v_h[j], vb);
                }
#pragma unroll
                for (int j = 0; j < 2; j++) {
                    mma16816(acc_o[(hf * 2 + j) * 2],     p_h, v_h[j]);
                    mma16816(acc_o[(hf * 2 + j) * 2 + 1], p_h, v_h[j] + 2);
                }
            }
        }
    }

    // epilogue: x hi-only fp16
    const float inva = 1.f / l_a, invb = 1.f / l_b;
#pragma unroll
    for (int nt = 0; nt < 8; nt++) {
        const int col = h * Dk + nt * 8 + qc * 2;
        size_t idx = ((size_t)b * Ssz + row_a) * Dm + col;
        *(uint32_t*)&xh[idx] = pack_f16(acc_o[nt][0] * inva, acc_o[nt][1] * inva);
        idx = ((size_t)b * Ssz + row_a + 8) * Dm + col;
        *(uint32_t*)&xh[idx] = pack_f16(acc_o[nt][2] * invb, acc_o[nt][3] * invb);
    }
}

// ---------------- launch ----------------------------------------------------
extern "C" void kernel_launch(void* const* d_in, const int* in_sizes, int n_in,
                              void* d_out, int out_size)
{
    (void)in_sizes; (void)n_in; (void)out_size;
    const float* query  = (const float*)d_in[0];
    const float* key_in = (const float*)d_in[1];
    const float* value  = (const float*)d_in[2];
    const int*   mask   = (const int*)  d_in[3];
    const float* Wq = (const float*)d_in[4];
    const float* bq = (const float*)d_in[5];
    const float* Wk = (const float*)d_in[6];
    const float* bk = (const float*)d_in[7];
    const float* Wv = (const float*)d_in[8];
    const float* bv = (const float*)d_in[9];
    const float* Wo = (const float*)d_in[10];
    const float* bo = (const float*)d_in[11];
    float* out = (float*)d_out;

    __half* ah;
    uint32_t* mbp;
    cudaGetSymbolAddress((void**)&ah, g_ah);
    cudaGetSymbolAddress((void**)&mbp, g_mb);

    cudaFuncSetAttribute(tgemm<0>, cudaFuncAttributeMaxDynamicSharedMemorySize, GEMM_SMEM);
    cudaFuncSetAttribute(tgemm<1>, cudaFuncAttributeMaxDynamicSharedMemorySize, GEMM_SMEM);
    cudaFuncSetAttribute(flash, cudaFuncAttributeMaxDynamicSharedMemorySize, FLASH_SMEM);

    // mask pack
    maskpack_kernel<<<(Bsz * Ssz * Ssz) / 256, 256>>>(mask, mbp);
    // fused conversions
    dim3 wgrid((Dm * Dm / 4) / 256, 1, 4);
    cvtW_kernel<<<wgrid, 256>>>(Wq, Wk, Wv, Wo);
    dim3 agrid((int)((MD / 4) / 256), 1, 3);
    cvtA_kernel<<<agrid, 256>>>(query, key_in, value);
    // fused Q/K/V projections
    dim3 pgrid(Dm / 128, 8192 / 128, 3);
    tgemm<1><<<pgrid, 256, GEMM_SMEM>>>(bq, bk, bv, nullptr);
    // attention (x hi -> activation slot 0)
    dim3 fgrid(Ssz / FQ, Hh, Bsz);
    flash<<<fgrid, 256, FLASH_SMEM>>>(mbp, ah);
    // output projection
    dim3 ogrid(Dm / 128, 8192 / 128);
    tgemm<0><<<ogrid, 256, GEMM_SMEM>>>(bo, nullptr, nullptr, out);
}

// round 14
// speedup vs baseline: 1.5519x; 1.0584x over previous
#include <cuda_runtime.h>
#include <cuda_fp16.h>
#include <math_constants.h>
#include <cstdint>

#define Bsz 4
#define Ssz 2048
#define Dm  1024
#define Hh  16
#define Dk  64
#define BH  (Bsz * Hh)
#define MD  ((size_t)8192 * 1024)
#define DD  ((size_t)1024 * 1024)

// ---------------- scratch (device globals; no allocation allowed) ----------
__device__ __align__(1024) __half g_qh[MD];            // Q hi (head-split, pre-scaled by 1/8)
__device__ __align__(1024) __half g_kh[MD];            // K hi
__device__ __align__(1024) __half g_vh[MD];            // V hi
__device__ __align__(1024) __half g_ah[3 * MD];        // activations hi (q,k,v); slot0 reused for x
__device__ __align__(1024) __half g_wh[4 * DD];        // weights hi (Wq,Wk,Wv,Wo)
__device__ __align__(1024) uint32_t g_mb[(size_t)Bsz * Ssz * (Ssz / 32)];

// ---------------- PTX helpers ----------------------------------------------
__device__ __forceinline__ uint32_t smem_u32(const void* p) {
    uint32_t a;
    asm("{ .reg .u64 t; cvta.to.shared.u64 t, %1; cvt.u32.u64 %0, t; }" : "=r"(a) : "l"(p));
    return a;
}
__device__ __forceinline__ void cp16(uint32_t dst, const void* src) {
    asm volatile("cp.async.cg.shared.global [%0], [%1], 16;" :: "r"(dst), "l"(src));
}
__device__ __forceinline__ void cp_commit() { asm volatile("cp.async.commit_group;"); }
__device__ __forceinline__ void cp_wait0()  { asm volatile("cp.async.wait_group 0;"); }

__device__ __forceinline__ void ldsm4(uint32_t* r, uint32_t a) {
    asm volatile("ldmatrix.sync.aligned.m8n8.x4.shared.b16 {%0,%1,%2,%3}, [%4];"
                 : "=r"(r[0]), "=r"(r[1]), "=r"(r[2]), "=r"(r[3]) : "r"(a));
}
__device__ __forceinline__ void ldsm4t(uint32_t* r, uint32_t a) {
    asm volatile("ldmatrix.sync.aligned.m8n8.x4.trans.shared.b16 {%0,%1,%2,%3}, [%4];"
                 : "=r"(r[0]), "=r"(r[1]), "=r"(r[2]), "=r"(r[3]) : "r"(a));
}
__device__ __forceinline__ void mma16816(float* d, const uint32_t* a, const uint32_t* b) {
    asm volatile("mma.sync.aligned.m16n8k16.row.col.f32.f16.f16.f32 "
                 "{%0,%1,%2,%3}, {%4,%5,%6,%7}, {%8,%9}, {%0,%1,%2,%3};"
                 : "+f"(d[0]), "+f"(d[1]), "+f"(d[2]), "+f"(d[3])
                 : "r"(a[0]), "r"(a[1]), "r"(a[2]), "r"(a[3]), "r"(b[0]), "r"(b[1]));
}
__device__ __forceinline__ uint32_t pack_f16(float lo, float hi) {
    uint32_t r;
    asm("cvt.rn.f16x2.f32 %0, %1, %2;" : "=r"(r) : "f"(hi), "f"(lo));
    return r;
}
__device__ __forceinline__ float qmax(float v) {
    v = fmaxf(v, __shfl_xor_sync(0xffffffffu, v, 1));
    v = fmaxf(v, __shfl_xor_sync(0xffffffffu, v, 2));
    return v;
}
__device__ __forceinline__ float qsum(float v) {
    v += __shfl_xor_sync(0xffffffffu, v, 1);
    v += __shfl_xor_sync(0xffffffffu, v, 2);
    return v;
}

// ---------------- fused prep: W cvt + A cvt + mask pack ---------------------
// grid.x layout: [0,4096) W convert (4 x 1024), [4096,28672) A convert (3 x 8192),
//                [28672,32768) mask pack (4096 CTAs x 16 chunks)
__global__ __launch_bounds__(256)
void prep_kernel(const float* __restrict__ q0, const float* __restrict__ k0,
                 const float* __restrict__ v0, const int* __restrict__ mask,
                 const float* __restrict__ w0, const float* __restrict__ w1,
                 const float* __restrict__ w2, const float* __restrict__ w3)
{
    const int bid = blockIdx.x;
    const int tid = threadIdx.x;
    if (bid < 4096) {
        const int z = bid >> 10;
        const float* src = (z == 0) ? w0 : (z == 1) ? w1 : (z == 2) ? w2 : w3;
        __half* hi = g_wh + (size_t)z * DD;
        const int i = (bid & 1023) * 256 + tid;
        float4 v = ((const float4*)src)[i];
        ((uint2*)hi)[i] = make_uint2(pack_f16(v.x, v.y), pack_f16(v.z, v.w));
    } else if (bid < 28672) {
        const int r = bid - 4096;
        const int z = r / 8192, rem = r % 8192;
        const float* src = (z == 0) ? q0 : (z == 1) ? k0 : v0;
        __half* hi = g_ah + (size_t)z * MD;
        const int i = rem * 256 + tid;
        float4 v = ((const float4*)src)[i];
        ((uint2*)hi)[i] = make_uint2(pack_f16(v.x, v.y), pack_f16(v.z, v.w));
    } else {
        const int r = bid - 28672;                       // 0..4095
#pragma unroll
        for (int it = 0; it < 16; it++) {
            const int i = (r * 16 + it) * 256 + tid;
            const uint32_t b = __ballot_sync(0xffffffffu, mask[i] != 0);
            if ((tid & 31) == 0) g_mb[i >> 5] = b;
        }
    }
}

// ---------------- tensor-core 1-pass fp16 GEMM ------------------------------
#define GSTRIDE 80
#define GARR    10240
#define GSTAGE  20480            // 2 arrays (Ah, Wh)
#define GEMM_SMEM (2 * GSTAGE)

__device__ __forceinline__ void gemm_load(uint32_t sb, int stage, int c, int tid,
                                          int m0, int n0,
                                          const __half* Ah, const __half* Wh)
{
#pragma unroll
    for (int it = 0; it < 4; it++) {
        const int flat = it * 256 + tid;                 // 0..1023
        const int arr = flat >> 9, rem = flat & 511;
        const int row = rem >> 2, seg = rem & 3;
        const __half* src = (arr == 0) ? Ah : Wh;
        const int gbase = (arr == 0) ? m0 : n0;
        cp16(sb + stage * GSTAGE + arr * GARR + row * GSTRIDE + seg * 16,
             src + (size_t)(gbase + row) * Dm + c * 32 + seg * 8);
    }
    cp_commit();
}

// MODE 0: output projection -> fp32 C.  MODE 1: per-z projection -> head-split fp16 hi.
template <int MODE>
__global__ __launch_bounds__(256, 2)
void tgemm(const float* __restrict__ b0p, const float* __restrict__ b1p,
           const float* __restrict__ b2p, float* __restrict__ C)
{
    extern __shared__ char smem[];
    const uint32_t sb = smem_u32(smem);
    const int tid = threadIdx.x;
    const int lane = tid & 31, w = tid >> 5;
    const int wm = w >> 1, wn = w & 1;
    const int m0 = blockIdx.y * 128, n0 = blockIdx.x * 128;
    const int z = (MODE == 1) ? blockIdx.z : 3;

    const __half* Ah = g_ah + ((MODE == 1) ? (size_t)z * MD : 0);
    const __half* Wh = g_wh + (size_t)z * DD;
    const float* bias = (MODE == 0) ? b0p : (z == 0) ? b0p : (z == 1) ? b1p : b2p;
    __half* Oh = (MODE == 1) ? ((z == 0) ? g_qh : (z == 1) ? g_kh : g_vh) : nullptr;

    float acc[2][8][4];
#pragma unroll
    for (int mt = 0; mt < 2; mt++)
#pragma unroll
        for (int nt = 0; nt < 8; nt++)
#pragma unroll
            for (int r = 0; r < 4; r++) acc[mt][nt][r] = 0.f;

    gemm_load(sb, 0, 0, tid, m0, n0, Ah, Wh);

    for (int c = 0; c < 32; c++) {
        cp_wait0();
        __syncthreads();
        if (c + 1 < 32) gemm_load(sb, (c + 1) & 1, c + 1, tid, m0, n0, Ah, Wh);
        const uint32_t st = sb + (c & 1) * GSTAGE;
#pragma unroll
        for (int kt = 0; kt < 2; kt++) {
            uint32_t a_h[2][4];
#pragma unroll
            for (int mt = 0; mt < 2; mt++) {
                const uint32_t ra = st +
                    (uint32_t)(wm * 32 + mt * 16 + ((lane >> 3) & 1) * 8 + (lane & 7)) * GSTRIDE +
                    kt * 32 + (lane >> 4) * 16;
                ldsm4(a_h[mt], ra);
            }
#pragma unroll
            for (int hf = 0; hf < 2; hf++) {
                uint32_t b_h[2][4];
#pragma unroll
                for (int j = 0; j < 2; j++) {
                    const int nt2 = hf * 2 + j;
                    const uint32_t rb = st + GARR +
                        (uint32_t)(wn * 64 + nt2 * 16 + (lane >> 4) * 8 + (lane & 7)) * GSTRIDE +
                        kt * 32 + ((lane >> 3) & 1) * 16;
                    ldsm4(b_h[j], rb);
                }
#pragma unroll
                for (int mt = 0; mt < 2; mt++)
#pragma unroll
                    for (int j = 0; j < 2; j++) {
                        mma16816(acc[mt][(hf * 2 + j) * 2],     a_h[mt], b_h[j]);
                        mma16816(acc[mt][(hf * 2 + j) * 2 + 1], a_h[mt], b_h[j] + 2);
                    }
            }
        }
    }

    const int grp = lane >> 2, qc = lane & 3;
#pragma unroll
    for (int mt = 0; mt < 2; mt++) {
#pragma unroll
        for (int nt = 0; nt < 8; nt++) {
            const int row = m0 + wm * 32 + mt * 16 + grp;
            const int col = n0 + wn * 64 + nt * 8 + qc * 2;
            const float b0 = bias[col], b1 = bias[col + 1];
            float v0 = acc[mt][nt][0] + b0, v1 = acc[mt][nt][1] + b1;
            float v2 = acc[mt][nt][2] + b0, v3 = acc[mt][nt][3] + b1;
            if (MODE == 0) {
                *(float2*)&C[(size_t)row * Dm + col]       = make_float2(v0, v1);
                *(float2*)&C[(size_t)(row + 8) * Dm + col] = make_float2(v2, v3);
            } else {
                if (z == 0) {   // fold softmax scale 1/8 into Q
                    v0 *= 0.125f; v1 *= 0.125f; v2 *= 0.125f; v3 *= 0.125f;
                }
                const int hh = col >> 6, dk = col & 63;
#pragma unroll
                for (int half_i = 0; half_i < 2; half_i++) {
                    const int r2 = row + half_i * 8;
                    const int bb = r2 >> 11, s = r2 & 2047;
                    const size_t idx = (((size_t)(bb * Hh + hh)) * Ssz + s) * Dk + dk;
                    const float x0 = half_i ? v2 : v0, x1 = half_i ? v3 : v1;
                    *(uint32_t*)&Oh[idx] = pack_f16(x0, x1);
                }
            }
        }
    }
}

// ---------------- flash attention: fp16, 1-pass QK, 1-pass PV ---------------
#define FQ 128
#define FK 64
#define FSTR 144
#define QH_OFF 0
#define KV_OFF 18432
#define KVST   18432            // per stage: kh, vh (9216 each)
#define VH_O 9216
#define FLASH_SMEM 55296        // 54 KB -> 2 CTAs/SM

__device__ __forceinline__ void flash_load_kv(uint32_t sb, int j, int tid, size_t bh)
{
#pragma unroll
    for (int it = 0; it < 4; it++) {
        const int flat = it * 256 + tid;                 // 0..1023
        const int arr = flat >> 9, rem = flat & 511;     // 0: kh, 1: vh
        const int row = rem >> 3, seg = rem & 7;
        const __half* src = (arr == 0) ? g_kh : g_vh;
        cp16(sb + KV_OFF + (j & 1) * KVST + arr * 9216 + row * FSTR + seg * 16,
             src + (bh * Ssz + j * FK + row) * Dk + seg * 8);
    }
    cp_commit();
}

__global__ __launch_bounds__(256, 2)
void flash(const uint32_t* __restrict__ mb, __half* __restrict__ xh)
{
    extern __shared__ char smem[];
    const uint32_t sb = smem_u32(smem);
    const int tid = threadIdx.x, lane = tid & 31, w = tid >> 5;
    const int b = blockIdx.z, h = blockIdx.y, q0 = blockIdx.x * FQ;
    const size_t bh = (size_t)(b * Hh + h);
    const int grp = lane >> 2, qc = lane & 3;
    const int row_a = q0 + w * 16 + grp;

    flash_load_kv(sb, 0, tid, bh);
#pragma unroll
    for (int it = 0; it < 4; it++) {
        const int flat = it * 256 + tid;                 // 0..1023
        const int row = flat >> 3, seg = flat & 7;
        cp16(sb + QH_OFF + row * FSTR + seg * 16,
             g_qh + (bh * Ssz + q0 + row) * Dk + seg * 8);
    }
    cp_commit();
    cp_wait0();
    __syncthreads();

    // hoist loop-invariant Q fragments (pre-scaled by 1/8)
    const uint32_t qrow = (uint32_t)(w * 16 + ((lane >> 3) & 1) * 8 + (lane & 7)) * FSTR +
                          (lane >> 4) * 16;
    uint32_t qfh[4][4];
#pragma unroll
    for (int kt = 0; kt < 4; kt++) ldsm4(qfh[kt], sb + QH_OFF + qrow + kt * 32);

    float acc_o[8][4];
#pragma unroll
    for (int nt = 0; nt < 8; nt++)
#pragma unroll
        for (int r = 0; r < 4; r++) acc_o[nt][r] = 0.f;
    float m_a = -CUDART_INF_F, m_b = -CUDART_INF_F, l_a = 0.f, l_b = 0.f;

    const uint32_t* mrow_a = mb + ((size_t)b * Ssz + row_a) * (Ssz / 32);
    const uint32_t* mrow_b = mrow_a + 8 * (Ssz / 32);

    const int NJT = Ssz / FK;   // 32
    for (int jt = 0; jt < NJT; jt++) {
        const uint2 wa = *(const uint2*)(mrow_a + jt * 2);
        const uint2 wb = *(const uint2*)(mrow_b + jt * 2);
        if (jt > 0) { cp_wait0(); __syncthreads(); }
        if (jt + 1 < NJT) flash_load_kv(sb, jt + 1, tid, bh);
        const uint32_t st = sb + KV_OFF + (jt & 1) * KVST;

        // ---- QK^T (scores arrive pre-scaled) ----
        float s[8][4];
#pragma unroll
        for (int nt = 0; nt < 8; nt++)
#pragma unroll
            for (int r = 0; r < 4; r++) s[nt][r] = 0.f;
#pragma unroll
        for (int kt = 0; kt < 4; kt++) {
#pragma unroll
            for (int hf = 0; hf < 2; hf++) {
                uint32_t b_h[2][4];
#pragma unroll
                for (int j = 0; j < 2; j++) {
                    const int nt2 = hf * 2 + j;
                    const uint32_t rb = st +
                        (uint32_t)(nt2 * 16 + (lane >> 4) * 8 + (lane & 7)) * FSTR +
                        kt * 32 + ((lane >> 3) & 1) * 16;
                    ldsm4(b_h[j], rb);
                }
#pragma unroll
                for (int j = 0; j < 2; j++) {
                    mma16816(s[(hf * 2 + j) * 2],     qfh[kt], b_h[j]);
                    mma16816(s[(hf * 2 + j) * 2 + 1], qfh[kt], b_h[j] + 2);
                }
            }
        }

        // ---- mask + online softmax (fp32 exp, fp32 sums) ----
        float ra = -CUDART_INF_F, rbx = -CUDART_INF_F;
#pragma unroll
        for (int nt = 0; nt < 8; nt++) {
            const int kk = nt * 8 + qc * 2;
            const uint32_t wA = (nt < 4) ? wa.x : wa.y;
            const uint32_t wB = (nt < 4) ? wb.x : wb.y;
            const int bit = kk & 31;
            s[nt][0] = ((wA >> bit) & 1)       ? s[nt][0] : -1e9f;
            s[nt][1] = ((wA >> (bit + 1)) & 1) ? s[nt][1] : -1e9f;
            s[nt][2] = ((wB >> bit) & 1)       ? s[nt][2] : -1e9f;
            s[nt][3] = ((wB >> (bit + 1)) & 1) ? s[nt][3] : -1e9f;
            ra  = fmaxf(ra,  fmaxf(s[nt][0], s[nt][1]));
            rbx = fmaxf(rbx, fmaxf(s[nt][2], s[nt][3]));
        }
        ra = qmax(ra); rbx = qmax(rbx);
        const float mna = fmaxf(m_a, ra), mnb = fmaxf(m_b, rbx);
        const float ca = __expf(m_a - mna), cb = __expf(m_b - mnb);
        float suma = 0.f, sumb = 0.f;
#pragma unroll
        for (int nt = 0; nt < 8; nt++) {
            s[nt][0] = __expf(s[nt][0] - mna);
            s[nt][1] = __expf(s[nt][1] - mna);
            s[nt][2] = __expf(s[nt][2] - mnb);
            s[nt][3] = __expf(s[nt][3] - mnb);
            suma += s[nt][0] + s[nt][1];
            sumb += s[nt][2] + s[nt][3];
        }
        l_a = l_a * ca + qsum(suma);
        l_b = l_b * cb + qsum(sumb);
#pragma unroll
        for (int nt = 0; nt < 8; nt++) {
            acc_o[nt][0] *= ca; acc_o[nt][1] *= ca;
            acc_o[nt][2] *= cb; acc_o[nt][3] *= cb;
        }
        m_a = mna; m_b = mnb;

        // ---- P @ V: single pass, P rounded to fp16 in registers ----
#pragma unroll
        for (int kt2 = 0; kt2 < 4; kt2++) {
            uint32_t p_h[4];
            p_h[0] = pack_f16(s[2 * kt2][0],     s[2 * kt2][1]);
            p_h[1] = pack_f16(s[2 * kt2][2],     s[2 * kt2][3]);
            p_h[2] = pack_f16(s[2 * kt2 + 1][0], s[2 * kt2 + 1][1]);
            p_h[3] = pack_f16(s[2 * kt2 + 1][2], s[2 * kt2 + 1][3]);
#pragma unroll
            for (int hf = 0; hf < 2; hf++) {
                uint32_t v_h[2][4];
#pragma unroll
                for (int j = 0; j < 2; j++) {
                    const int nd2 = hf * 2 + j;
                    const uint32_t vb = st + VH_O +
                        (uint32_t)(kt2 * 16 + ((lane >> 3) & 1) * 8 + (lane & 7)) * FSTR +
                        nd2 * 32 + (lane >> 4) * 16;
                    ldsm4t(v_h[j], vb);
                }
#pragma unroll
                for (int j = 0; j < 2; j++) {
                    mma16816(acc_o[(hf * 2 + j) * 2],     p_h, v_h[j]);
                    mma16816(acc_o[(hf * 2 + j) * 2 + 1], p_h, v_h[j] + 2);
                }
            }
        }
    }

    // epilogue: x hi-only fp16
    const float inva = 1.f / l_a, invb = 1.f / l_b;
#pragma unroll
    for (int nt = 0; nt < 8; nt++) {
        const int col = h * Dk + nt * 8 + qc * 2;
        size_t idx = ((size_t)b * Ssz + row_a) * Dm + col;
        *(uint32_t*)&xh[idx] = pack_f16(acc_o[nt][0] * inva, acc_o[nt][1] * inva);
        idx = ((size_t)b * Ssz + row_a + 8) * Dm + col;
        *(uint32_t*)&xh[idx] = pack_f16(acc_o[nt][2] * invb, acc_o[nt][3] * invb);
    }
}

// ---------------- launch ----------------------------------------------------
extern "C" void kernel_launch(void* const* d_in, const int* in_sizes, int n_in,
                              void* d_out, int out_size)
{
    (void)in_sizes; (void)n_in; (void)out_size;
    const float* query  = (const float*)d_in[0];
    const float* key_in = (const float*)d_in[1];
    const float* value  = (const float*)d_in[2];
    const int*   mask   = (const int*)  d_in[3];
    const float* Wq = (const float*)d_in[4];
    const float* bq = (const float*)d_in[5];
    const float* Wk = (const float*)d_in[6];
    const float* bk = (const float*)d_in[7];
    const float* Wv = (const float*)d_in[8];
    const float* bv = (const float*)d_in[9];
    const float* Wo = (const float*)d_in[10];
    const float* bo = (const float*)d_in[11];
    float* out = (float*)d_out;

    __half* ah;
    uint32_t* mbp;
    cudaGetSymbolAddress((void**)&ah, g_ah);
    cudaGetSymbolAddress((void**)&mbp, g_mb);

    cudaFuncSetAttribute(tgemm<0>, cudaFuncAttributeMaxDynamicSharedMemorySize, GEMM_SMEM);
    cudaFuncSetAttribute(tgemm<1>, cudaFuncAttributeMaxDynamicSharedMemorySize, GEMM_SMEM);
    cudaFuncSetAttribute(flash, cudaFuncAttributeMaxDynamicSharedMemorySize, FLASH_SMEM);

    // fused prep: W/A conversion + mask pack, one launch
    prep_kernel<<<32768, 256>>>(query, key_in, value, mask, Wq, Wk, Wv, Wo);
    // fused Q/K/V projections
    dim3 pgrid(Dm / 128, 8192 / 128, 3);
    tgemm<1><<<pgrid, 256, GEMM_SMEM>>>(bq, bk, bv, nullptr);
    // attention (x hi -> activation slot 0)
    dim3 fgrid(Ssz / FQ, Hh, Bsz);
    flash<<<fgrid, 256, FLASH_SMEM>>>(mbp, ah);
    // output projection
    dim3 ogrid(Dm / 128, 8192 / 128);
    tgemm<0><<<ogrid, 256, GEMM_SMEM>>>(bo, nullptr, nullptr, out);
}

// round 15
// speedup vs baseline: 1.5863x; 1.0222x over previous
#include <cuda_runtime.h>
#include <cuda_fp16.h>
#include <math_constants.h>
#include <cstdint>

#define Bsz 4
#define Ssz 2048
#define Dm  1024
#define Hh  16
#define Dk  64
#define BH  (Bsz * Hh)
#define MD  ((size_t)8192 * 1024)
#define DD  ((size_t)1024 * 1024)

// ---------------- scratch (device globals; no allocation allowed) ----------
__device__ __align__(1024) __half g_qh[MD];            // Q hi (head-split, pre-scaled by 1/8)
__device__ __align__(1024) __half g_kh[MD];            // K hi
__device__ __align__(1024) __half g_vh[MD];            // V hi
__device__ __align__(1024) __half g_ah[3 * MD];        // activations hi (q,k,v); slot0 reused for x
__device__ __align__(1024) __half g_wh[4 * DD];        // weights hi (Wq,Wk,Wv,Wo)
__device__ __align__(1024) uint32_t g_mb[(size_t)Bsz * Ssz * (Ssz / 32)];

// ---------------- PTX helpers ----------------------------------------------
__device__ __forceinline__ uint32_t smem_u32(const void* p) {
    uint32_t a;
    asm("{ .reg .u64 t; cvta.to.shared.u64 t, %1; cvt.u32.u64 %0, t; }" : "=r"(a) : "l"(p));
    return a;
}
__device__ __forceinline__ void cp16(uint32_t dst, const void* src) {
    asm volatile("cp.async.cg.shared.global [%0], [%1], 16;" :: "r"(dst), "l"(src));
}
__device__ __forceinline__ void cp_commit() { asm volatile("cp.async.commit_group;"); }
__device__ __forceinline__ void cp_wait0()  { asm volatile("cp.async.wait_group 0;"); }

__device__ __forceinline__ void ldsm4(uint32_t* r, uint32_t a) {
    asm volatile("ldmatrix.sync.aligned.m8n8.x4.shared.b16 {%0,%1,%2,%3}, [%4];"
                 : "=r"(r[0]), "=r"(r[1]), "=r"(r[2]), "=r"(r[3]) : "r"(a));
}
__device__ __forceinline__ void ldsm4t(uint32_t* r, uint32_t a) {
    asm volatile("ldmatrix.sync.aligned.m8n8.x4.trans.shared.b16 {%0,%1,%2,%3}, [%4];"
                 : "=r"(r[0]), "=r"(r[1]), "=r"(r[2]), "=r"(r[3]) : "r"(a));
}
__device__ __forceinline__ void mma16816(float* d, const uint32_t* a, const uint32_t* b) {
    asm volatile("mma.sync.aligned.m16n8k16.row.col.f32.f16.f16.f32 "
                 "{%0,%1,%2,%3}, {%4,%5,%6,%7}, {%8,%9}, {%0,%1,%2,%3};"
                 : "+f"(d[0]), "+f"(d[1]), "+f"(d[2]), "+f"(d[3])
                 : "r"(a[0]), "r"(a[1]), "r"(a[2]), "r"(a[3]), "r"(b[0]), "r"(b[1]));
}
__device__ __forceinline__ uint32_t pack_f16(float lo, float hi) {
    uint32_t r;
    asm("cvt.rn.f16x2.f32 %0, %1, %2;" : "=r"(r) : "f"(hi), "f"(lo));
    return r;
}
__device__ __forceinline__ float qmax(float v) {
    v = fmaxf(v, __shfl_xor_sync(0xffffffffu, v, 1));
    v = fmaxf(v, __shfl_xor_sync(0xffffffffu, v, 2));
    return v;
}
__device__ __forceinline__ float qsum(float v) {
    v += __shfl_xor_sync(0xffffffffu, v, 1);
    v += __shfl_xor_sync(0xffffffffu, v, 2);
    return v;
}

// ---------------- fused prep: W cvt + A cvt + mask pack ---------------------
__global__ __launch_bounds__(256)
void prep_kernel(const float* __restrict__ q0, const float* __restrict__ k0,
                 const float* __restrict__ v0, const int* __restrict__ mask,
                 const float* __restrict__ w0, const float* __restrict__ w1,
                 const float* __restrict__ w2, const float* __restrict__ w3)
{
    const int bid = blockIdx.x;
    const int tid = threadIdx.x;
    if (bid < 4096) {
        const int z = bid >> 10;
        const float* src = (z == 0) ? w0 : (z == 1) ? w1 : (z == 2) ? w2 : w3;
        __half* hi = g_wh + (size_t)z * DD;
        const int i = (bid & 1023) * 256 + tid;
        float4 v = ((const float4*)src)[i];
        ((uint2*)hi)[i] = make_uint2(pack_f16(v.x, v.y), pack_f16(v.z, v.w));
    } else if (bid < 28672) {
        const int r = bid - 4096;
        const int z = r / 8192, rem = r % 8192;
        const float* src = (z == 0) ? q0 : (z == 1) ? k0 : v0;
        __half* hi = g_ah + (size_t)z * MD;
        const int i = rem * 256 + tid;
        float4 v = ((const float4*)src)[i];
        ((uint2*)hi)[i] = make_uint2(pack_f16(v.x, v.y), pack_f16(v.z, v.w));
    } else {
        const int r = bid - 28672;
#pragma unroll
        for (int it = 0; it < 16; it++) {
            const int i = (r * 16 + it) * 256 + tid;
            const uint32_t b = __ballot_sync(0xffffffffu, mask[i] != 0);
            if ((tid & 31) == 0) g_mb[i >> 5] = b;
        }
    }
}

// ---------------- tensor-core 1-pass fp16 GEMM (BK=64) ----------------------
#define GSTRIDE 144
#define GARR    18432            // 128 rows x 144 B
#define GSTAGE  36864            // Ah + Wh
#define GEMM_SMEM (2 * GSTAGE)   // 73728 -> 2 CTAs/SM

__device__ __forceinline__ void gemm_load(uint32_t sb, int stage, int c, int tid,
                                          int m0, int n0,
                                          const __half* Ah, const __half* Wh)
{
#pragma unroll
    for (int it = 0; it < 8; it++) {
        const int flat = it * 256 + tid;                 // 0..2047
        const int arr = flat >> 10, rem = flat & 1023;
        const int row = rem >> 3, seg = rem & 7;
        const __half* src = (arr == 0) ? Ah : Wh;
        const int gbase = (arr == 0) ? m0 : n0;
        cp16(sb + stage * GSTAGE + arr * GARR + row * GSTRIDE + seg * 16,
             src + (size_t)(gbase + row) * Dm + c * 64 + seg * 8);
    }
    cp_commit();
}

// MODE 0: output projection -> fp32 C.  MODE 1: per-z projection -> head-split fp16 hi.
template <int MODE>
__global__ __launch_bounds__(256, 2)
void tgemm(const float* __restrict__ b0p, const float* __restrict__ b1p,
           const float* __restrict__ b2p, float* __restrict__ C)
{
    extern __shared__ char smem[];
    const uint32_t sb = smem_u32(smem);
    const int tid = threadIdx.x;
    const int lane = tid & 31, w = tid >> 5;
    const int wm = w >> 1, wn = w & 1;
    const int m0 = blockIdx.y * 128, n0 = blockIdx.x * 128;
    const int z = (MODE == 1) ? blockIdx.z : 3;

    const __half* Ah = g_ah + ((MODE == 1) ? (size_t)z * MD : 0);
    const __half* Wh = g_wh + (size_t)z * DD;
    const float* bias = (MODE == 0) ? b0p : (z == 0) ? b0p : (z == 1) ? b1p : b2p;
    __half* Oh = (MODE == 1) ? ((z == 0) ? g_qh : (z == 1) ? g_kh : g_vh) : nullptr;

    float acc[2][8][4];
#pragma unroll
    for (int mt = 0; mt < 2; mt++)
#pragma unroll
        for (int nt = 0; nt < 8; nt++)
#pragma unroll
            for (int r = 0; r < 4; r++) acc[mt][nt][r] = 0.f;

    gemm_load(sb, 0, 0, tid, m0, n0, Ah, Wh);

    for (int c = 0; c < 16; c++) {
        cp_wait0();
        __syncthreads();
        if (c + 1 < 16) gemm_load(sb, (c + 1) & 1, c + 1, tid, m0, n0, Ah, Wh);
        const uint32_t st = sb + (c & 1) * GSTAGE;
#pragma unroll
        for (int kt = 0; kt < 4; kt++) {
            uint32_t a_h[2][4];
#pragma unroll
            for (int mt = 0; mt < 2; mt++) {
                const uint32_t ra = st +
                    (uint32_t)(wm * 32 + mt * 16 + ((lane >> 3) & 1) * 8 + (lane & 7)) * GSTRIDE +
                    kt * 32 + (lane >> 4) * 16;
                ldsm4(a_h[mt], ra);
            }
#pragma unroll
            for (int hf = 0; hf < 2; hf++) {
                uint32_t b_h[2][4];
#pragma unroll
                for (int j = 0; j < 2; j++) {
                    const int nt2 = hf * 2 + j;
                    const uint32_t rb = st + GARR +
                        (uint32_t)(wn * 64 + nt2 * 16 + (lane >> 4) * 8 + (lane & 7)) * GSTRIDE +
                        kt * 32 + ((lane >> 3) & 1) * 16;
                    ldsm4(b_h[j], rb);
                }
#pragma unroll
                for (int mt = 0; mt < 2; mt++)
#pragma unroll
                    for (int j = 0; j < 2; j++) {
                        mma16816(acc[mt][(hf * 2 + j) * 2],     a_h[mt], b_h[j]);
                        mma16816(acc[mt][(hf * 2 + j) * 2 + 1], a_h[mt], b_h[j] + 2);
                    }
            }
        }
    }

    const int grp = lane >> 2, qc = lane & 3;
#pragma unroll
    for (int mt = 0; mt < 2; mt++) {
#pragma unroll
        for (int nt = 0; nt < 8; nt++) {
            const int row = m0 + wm * 32 + mt * 16 + grp;
            const int col = n0 + wn * 64 + nt * 8 + qc * 2;
            const float b0 = bias[col], b1 = bias[col + 1];
            float v0 = acc[mt][nt][0] + b0, v1 = acc[mt][nt][1] + b1;
            float v2 = acc[mt][nt][2] + b0, v3 = acc[mt][nt][3] + b1;
            if (MODE == 0) {
                *(float2*)&C[(size_t)row * Dm + col]       = make_float2(v0, v1);
                *(float2*)&C[(size_t)(row + 8) * Dm + col] = make_float2(v2, v3);
            } else {
                if (z == 0) { v0 *= 0.125f; v1 *= 0.125f; v2 *= 0.125f; v3 *= 0.125f; }
                const int hh = col >> 6, dk = col & 63;
#pragma unroll
                for (int half_i = 0; half_i < 2; half_i++) {
                    const int r2 = row + half_i * 8;
                    const int bb = r2 >> 11, s = r2 & 2047;
                    const size_t idx = (((size_t)(bb * Hh + hh)) * Ssz + s) * Dk + dk;
                    const float x0 = half_i ? v2 : v0, x1 = half_i ? v3 : v1;
                    *(uint32_t*)&Oh[idx] = pack_f16(x0, x1);
                }
            }
        }
    }
}

// ---------------- flash attention: 128-key stages, two 64-key sub-tiles -----
#define FQ 128
#define FKS 128                  // keys per stage
#define FSTR 144
#define QH_OFF 0
#define KV_OFF 18432
#define KARR 18432               // 128 rows x 144
#define KVST 36864               // kh + vh
#define VH_O 18432
#define FLASH_SMEM 92160         // 18432 + 2*36864 -> 2 CTAs/SM

__device__ __forceinline__ void flash_load_kv(uint32_t sb, int j, int tid, size_t bh)
{
#pragma unroll
    for (int it = 0; it < 8; it++) {
        const int flat = it * 256 + tid;                 // 0..2047
        const int arr = flat >> 10, rem = flat & 1023;   // 0: kh, 1: vh
        const int row = rem >> 3, seg = rem & 7;
        const __half* src = (arr == 0) ? g_kh : g_vh;
        cp16(sb + KV_OFF + (j & 1) * KVST + arr * KARR + row * FSTR + seg * 16,
             src + (bh * Ssz + j * FKS + row) * Dk + seg * 8);
    }
    cp_commit();
}

__global__ __launch_bounds__(256, 2)
void flash(const uint32_t* __restrict__ mb, __half* __restrict__ xh)
{
    extern __shared__ char smem[];
    const uint32_t sb = smem_u32(smem);
    const int tid = threadIdx.x, lane = tid & 31, w = tid >> 5;
    const int b = blockIdx.z, h = blockIdx.y, q0 = blockIdx.x * FQ;
    const size_t bh = (size_t)(b * Hh + h);
    const int grp = lane >> 2, qc = lane & 3;
    const int row_a = q0 + w * 16 + grp;

    flash_load_kv(sb, 0, tid, bh);
#pragma unroll
    for (int it = 0; it < 4; it++) {
        const int flat = it * 256 + tid;
        const int row = flat >> 3, seg = flat & 7;
        cp16(sb + QH_OFF + row * FSTR + seg * 16,
             g_qh + (bh * Ssz + q0 + row) * Dk + seg * 8);
    }
    cp_commit();
    cp_wait0();
    __syncthreads();

    const uint32_t qrow = (uint32_t)(w * 16 + ((lane >> 3) & 1) * 8 + (lane & 7)) * FSTR +
                          (lane >> 4) * 16;
    uint32_t qfh[4][4];
#pragma unroll
    for (int kt = 0; kt < 4; kt++) ldsm4(qfh[kt], sb + QH_OFF + qrow + kt * 32);

    float acc_o[8][4];
#pragma unroll
    for (int nt = 0; nt < 8; nt++)
#pragma unroll
        for (int r = 0; r < 4; r++) acc_o[nt][r] = 0.f;
    float m_a = -CUDART_INF_F, m_b = -CUDART_INF_F, l_a = 0.f, l_b = 0.f;

    const uint32_t* mrow_a = mb + ((size_t)b * Ssz + row_a) * (Ssz / 32);
    const uint32_t* mrow_b = mrow_a + 8 * (Ssz / 32);

    const int NJT = Ssz / FKS;   // 16
    for (int jt = 0; jt < NJT; jt++) {
        const uint4 wa = *(const uint4*)(mrow_a + jt * 4);
        const uint4 wb = *(const uint4*)(mrow_b + jt * 4);
        if (jt > 0) { cp_wait0(); __syncthreads(); }
        if (jt + 1 < NJT) flash_load_kv(sb, jt + 1, tid, bh);
        const uint32_t st = sb + KV_OFF + (jt & 1) * KVST;

#pragma unroll
        for (int half = 0; half < 2; half++) {
            const uint32_t kbase = st + (uint32_t)(half * 64) * FSTR;
            const uint32_t wax = half ? wa.z : wa.x, way = half ? wa.w : wa.y;
            const uint32_t wbx = half ? wb.z : wb.x, wby = half ? wb.w : wb.y;

            // ---- QK^T (scores pre-scaled via Q) ----
            float s[8][4];
#pragma unroll
            for (int nt = 0; nt < 8; nt++)
#pragma unroll
                for (int r = 0; r < 4; r++) s[nt][r] = 0.f;
#pragma unroll
            for (int kt = 0; kt < 4; kt++) {
#pragma unroll
                for (int hf = 0; hf < 2; hf++) {
                    uint32_t b_h[2][4];
#pragma unroll
                    for (int j = 0; j < 2; j++) {
                        const int nt2 = hf * 2 + j;
                        const uint32_t rb = kbase +
                            (uint32_t)(nt2 * 16 + (lane >> 4) * 8 + (lane & 7)) * FSTR +
                            kt * 32 + ((lane >> 3) & 1) * 16;
                        ldsm4(b_h[j], rb);
                    }
#pragma unroll
                    for (int j = 0; j < 2; j++) {
                        mma16816(s[(hf * 2 + j) * 2],     qfh[kt], b_h[j]);
                        mma16816(s[(hf * 2 + j) * 2 + 1], qfh[kt], b_h[j] + 2);
                    }
                }
            }

            // ---- mask + online softmax ----
            float ra = -CUDART_INF_F, rbx = -CUDART_INF_F;
#pragma unroll
            for (int nt = 0; nt < 8; nt++) {
                const int kk = nt * 8 + qc * 2;
                const uint32_t wA = (nt < 4) ? wax : way;
                const uint32_t wB = (nt < 4) ? wbx : wby;
                const int bit = kk & 31;
                s[nt][0] = ((wA >> bit) & 1)       ? s[nt][0] : -1e9f;
                s[nt][1] = ((wA >> (bit + 1)) & 1) ? s[nt][1] : -1e9f;
                s[nt][2] = ((wB >> bit) & 1)       ? s[nt][2] : -1e9f;
                s[nt][3] = ((wB >> (bit + 1)) & 1) ? s[nt][3] : -1e9f;
                ra  = fmaxf(ra,  fmaxf(s[nt][0], s[nt][1]));
                rbx = fmaxf(rbx, fmaxf(s[nt][2], s[nt][3]));
            }
            ra = qmax(ra); rbx = qmax(rbx);
            const float mna = fmaxf(m_a, ra), mnb = fmaxf(m_b, rbx);
            const float ca = __expf(m_a - mna), cb = __expf(m_b - mnb);
            float suma = 0.f, sumb = 0.f;
#pragma unroll
            for (int nt = 0; nt < 8; nt++) {
                s[nt][0] = __expf(s[nt][0] - mna);
                s[nt][1] = __expf(s[nt][1] - mna);
                s[nt][2] = __expf(s[nt][2] - mnb);
                s[nt][3] = __expf(s[nt][3] - mnb);
                suma += s[nt][0] + s[nt][1];
                sumb += s[nt][2] + s[nt][3];
            }
            l_a = l_a * ca + qsum(suma);
            l_b = l_b * cb + qsum(sumb);
#pragma unroll
            for (int nt = 0; nt < 8; nt++) {
                acc_o[nt][0] *= ca; acc_o[nt][1] *= ca;
                acc_o[nt][2] *= cb; acc_o[nt][3] *= cb;
            }
            m_a = mna; m_b = mnb;

            // ---- P @ V ----
#pragma unroll
            for (int kt2 = 0; kt2 < 4; kt2++) {
                uint32_t p_h[4];
                p_h[0] = pack_f16(s[2 * kt2][0],     s[2 * kt2][1]);
                p_h[1] = pack_f16(s[2 * kt2][2],     s[2 * kt2][3]);
                p_h[2] = pack_f16(s[2 * kt2 + 1][0], s[2 * kt2 + 1][1]);
                p_h[3] = pack_f16(s[2 * kt2 + 1][2], s[2 * kt2 + 1][3]);
#pragma unroll
                for (int hf = 0; hf < 2; hf++) {
                    uint32_t v_h[2][4];
#pragma unroll
                    for (int j = 0; j < 2; j++) {
                        const int nd2 = hf * 2 + j;
                        const uint32_t vb = st + VH_O +
                            (uint32_t)(half * 64 + kt2 * 16 + ((lane >> 3) & 1) * 8 + (lane & 7)) * FSTR +
                            nd2 * 32 + (lane >> 4) * 16;
                        ldsm4t(v_h[j], vb);
                    }
#pragma unroll
                    for (int j = 0; j < 2; j++) {
                        mma16816(acc_o[(hf * 2 + j) * 2],     p_h, v_h[j]);
                        mma16816(acc_o[(hf * 2 + j) * 2 + 1], p_h, v_h[j] + 2);
                    }
                }
            }
        }
    }

    // epilogue: x hi-only fp16
    const float inva = 1.f / l_a, invb = 1.f / l_b;
#pragma unroll
    for (int nt = 0; nt < 8; nt++) {
        const int col = h * Dk + nt * 8 + qc * 2;
        size_t idx = ((size_t)b * Ssz + row_a) * Dm + col;
        *(uint32_t*)&xh[idx] = pack_f16(acc_o[nt][0] * inva, acc_o[nt][1] * inva);
        idx = ((size_t)b * Ssz + row_a + 8) * Dm + col;
        *(uint32_t*)&xh[idx] = pack_f16(acc_o[nt][2] * invb, acc_o[nt][3] * invb);
    }
}

// ---------------- launch ----------------------------------------------------
extern "C" void kernel_launch(void* const* d_in, const int* in_sizes, int n_in,
                              void* d_out, int out_size)
{
    (void)in_sizes; (void)n_in; (void)out_size;
    const float* query  = (const float*)d_in[0];
    const float* key_in = (const float*)d_in[1];
    const float* value  = (const float*)d_in[2];
    const int*   mask   = (const int*)  d_in[3];
    const float* Wq = (const float*)d_in[4];
    const float* bq = (const float*)d_in[5];
    const float* Wk = (const float*)d_in[6];
    const float* bk = (const float*)d_in[7];
    const float* Wv = (const float*)d_in[8];
    const float* bv = (const float*)d_in[9];
    const float* Wo = (const float*)d_in[10];
    const float* bo = (const float*)d_in[11];
    float* out = (float*)d_out;

    __half* ah;
    uint32_t* mbp;
    cudaGetSymbolAddress((void**)&ah, g_ah);
    cudaGetSymbolAddress((void**)&mbp, g_mb);

    cudaFuncSetAttribute(tgemm<0>, cudaFuncAttributeMaxDynamicSharedMemorySize, GEMM_SMEM);
    cudaFuncSetAttribute(tgemm<1>, cudaFuncAttributeMaxDynamicSharedMemorySize, GEMM_SMEM);
    cudaFuncSetAttribute(flash, cudaFuncAttributeMaxDynamicSharedMemorySize, FLASH_SMEM);

    // fused prep: W/A conversion + mask pack
    prep_kernel<<<32768, 256>>>(query, key_in, value, mask, Wq, Wk, Wv, Wo);
    // fused Q/K/V projections
    dim3 pgrid(Dm / 128, 8192 / 128, 3);
    tgemm<1><<<pgrid, 256, GEMM_SMEM>>>(bq, bk, bv, nullptr);
    // attention (x hi -> activation slot 0)
    dim3 fgrid(Ssz / FQ, Hh, Bsz);
    flash<<<fgrid, 256, FLASH_SMEM>>>(mbp, ah);
    // output projection
    dim3 ogrid(Dm / 128, 8192 / 128);
    tgemm<0><<<ogrid, 256, GEMM_SMEM>>>(bo, nullptr, nullptr, out);
}

// round 16
// speedup vs baseline: 1.6148x; 1.0180x over previous
#include <cuda_runtime.h>
#include <cuda_fp16.h>
#include <math_constants.h>
#include <cstdint>

#define Bsz 4
#define Ssz 2048
#define Dm  1024
#define Hh  16
#define Dk  64
#define BH  (Bsz * Hh)
#define MD  ((size_t)8192 * 1024)
#define DD  ((size_t)1024 * 1024)

// ---------------- scratch (device globals; no allocation allowed) ----------
__device__ __align__(1024) __half g_qh[MD];            // Q hi (head-split, pre-scaled by 1/8)
__device__ __align__(1024) __half g_kh[MD];            // K hi
__device__ __align__(1024) __half g_vh[MD];            // V hi
__device__ __align__(1024) __half g_ah[3 * MD];        // activations hi (q,k,v); slot0 reused for x
__device__ __align__(1024) __half g_wh[4 * DD];        // weights hi (Wq,Wk,Wv,Wo)
__device__ __align__(1024) uint32_t g_mb[(size_t)Bsz * Ssz * (Ssz / 32)];

// ---------------- PTX helpers ----------------------------------------------
__device__ __forceinline__ uint32_t smem_u32(const void* p) {
    uint32_t a;
    asm("{ .reg .u64 t; cvta.to.shared.u64 t, %1; cvt.u32.u64 %0, t; }" : "=r"(a) : "l"(p));
    return a;
}
__device__ __forceinline__ void cp16(uint32_t dst, const void* src) {
    asm volatile("cp.async.cg.shared.global [%0], [%1], 16;" :: "r"(dst), "l"(src));
}
__device__ __forceinline__ void cp_commit() { asm volatile("cp.async.commit_group;"); }
__device__ __forceinline__ void cp_wait0()  { asm volatile("cp.async.wait_group 0;"); }

__device__ __forceinline__ void ldsm4(uint32_t* r, uint32_t a) {
    asm volatile("ldmatrix.sync.aligned.m8n8.x4.shared.b16 {%0,%1,%2,%3}, [%4];"
                 : "=r"(r[0]), "=r"(r[1]), "=r"(r[2]), "=r"(r[3]) : "r"(a));
}
__device__ __forceinline__ void ldsm4t(uint32_t* r, uint32_t a) {
    asm volatile("ldmatrix.sync.aligned.m8n8.x4.trans.shared.b16 {%0,%1,%2,%3}, [%4];"
                 : "=r"(r[0]), "=r"(r[1]), "=r"(r[2]), "=r"(r[3]) : "r"(a));
}
__device__ __forceinline__ void mma16816(float* d, const uint32_t* a, const uint32_t* b) {
    asm volatile("mma.sync.aligned.m16n8k16.row.col.f32.f16.f16.f32 "
                 "{%0,%1,%2,%3}, {%4,%5,%6,%7}, {%8,%9}, {%0,%1,%2,%3};"
                 : "+f"(d[0]), "+f"(d[1]), "+f"(d[2]), "+f"(d[3])
                 : "r"(a[0]), "r"(a[1]), "r"(a[2]), "r"(a[3]), "r"(b[0]), "r"(b[1]));
}
// fp16-accumulate variant (D, C are f16x2 pairs)
__device__ __forceinline__ void mma16816h(uint32_t* d, const uint32_t* a, const uint32_t* b) {
    asm volatile("mma.sync.aligned.m16n8k16.row.col.f16.f16.f16.f16 "
                 "{%0,%1}, {%2,%3,%4,%5}, {%6,%7}, {%0,%1};"
                 : "+r"(d[0]), "+r"(d[1])
                 : "r"(a[0]), "r"(a[1]), "r"(a[2]), "r"(a[3]), "r"(b[0]), "r"(b[1]));
}
__device__ __forceinline__ uint32_t pack_f16(float lo, float hi) {
    uint32_t r;
    asm("cvt.rn.f16x2.f32 %0, %1, %2;" : "=r"(r) : "f"(hi), "f"(lo));
    return r;
}
__device__ __forceinline__ float qmax(float v) {
    v = fmaxf(v, __shfl_xor_sync(0xffffffffu, v, 1));
    v = fmaxf(v, __shfl_xor_sync(0xffffffffu, v, 2));
    return v;
}
__device__ __forceinline__ float qsum(float v) {
    v += __shfl_xor_sync(0xffffffffu, v, 1);
    v += __shfl_xor_sync(0xffffffffu, v, 2);
    return v;
}

// ---------------- fused prep: W cvt + A cvt + mask pack ---------------------
__global__ __launch_bounds__(256)
void prep_kernel(const float* __restrict__ q0, const float* __restrict__ k0,
                 const float* __restrict__ v0, const int* __restrict__ mask,
                 const float* __restrict__ w0, const float* __restrict__ w1,
                 const float* __restrict__ w2, const float* __restrict__ w3)
{
    const int bid = blockIdx.x;
    const int tid = threadIdx.x;
    if (bid < 4096) {
        const int z = bid >> 10;
        const float* src = (z == 0) ? w0 : (z == 1) ? w1 : (z == 2) ? w2 : w3;
        __half* hi = g_wh + (size_t)z * DD;
        const int i = (bid & 1023) * 256 + tid;
        float4 v = ((const float4*)src)[i];
        ((uint2*)hi)[i] = make_uint2(pack_f16(v.x, v.y), pack_f16(v.z, v.w));
    } else if (bid < 28672) {
        const int r = bid - 4096;
        const int z = r / 8192, rem = r % 8192;
        const float* src = (z == 0) ? q0 : (z == 1) ? k0 : v0;
        __half* hi = g_ah + (size_t)z * MD;
        const int i = rem * 256 + tid;
        float4 v = ((const float4*)src)[i];
        ((uint2*)hi)[i] = make_uint2(pack_f16(v.x, v.y), pack_f16(v.z, v.w));
    } else {
        const int r = bid - 28672;
#pragma unroll
        for (int it = 0; it < 16; it++) {
            const int i = (r * 16 + it) * 256 + tid;
            const uint32_t b = __ballot_sync(0xffffffffu, mask[i] != 0);
            if ((tid & 31) == 0) g_mb[i >> 5] = b;
        }
    }
}

// ---------------- tensor-core 1-pass fp16 GEMM (BK=64) ----------------------
#define GSTRIDE 144
#define GARR    18432
#define GSTAGE  36864
#define GEMM_SMEM (2 * GSTAGE)

__device__ __forceinline__ void gemm_load(uint32_t sb, int stage, int c, int tid,
                                          int m0, int n0,
                                          const __half* Ah, const __half* Wh)
{
#pragma unroll
    for (int it = 0; it < 8; it++) {
        const int flat = it * 256 + tid;
        const int arr = flat >> 10, rem = flat & 1023;
        const int row = rem >> 3, seg = rem & 7;
        const __half* src = (arr == 0) ? Ah : Wh;
        const int gbase = (arr == 0) ? m0 : n0;
        cp16(sb + stage * GSTAGE + arr * GARR + row * GSTRIDE + seg * 16,
             src + (size_t)(gbase + row) * Dm + c * 64 + seg * 8);
    }
    cp_commit();
}

template <int MODE>
__global__ __launch_bounds__(256, 2)
void tgemm(const float* __restrict__ b0p, const float* __restrict__ b1p,
           const float* __restrict__ b2p, float* __restrict__ C)
{
    extern __shared__ char smem[];
    const uint32_t sb = smem_u32(smem);
    const int tid = threadIdx.x;
    const int lane = tid & 31, w = tid >> 5;
    const int wm = w >> 1, wn = w & 1;
    const int m0 = blockIdx.y * 128, n0 = blockIdx.x * 128;
    const int z = (MODE == 1) ? blockIdx.z : 3;

    const __half* Ah = g_ah + ((MODE == 1) ? (size_t)z * MD : 0);
    const __half* Wh = g_wh + (size_t)z * DD;
    const float* bias = (MODE == 0) ? b0p : (z == 0) ? b0p : (z == 1) ? b1p : b2p;
    __half* Oh = (MODE == 1) ? ((z == 0) ? g_qh : (z == 1) ? g_kh : g_vh) : nullptr;

    float acc[2][8][4];
#pragma unroll
    for (int mt = 0; mt < 2; mt++)
#pragma unroll
        for (int nt = 0; nt < 8; nt++)
#pragma unroll
            for (int r = 0; r < 4; r++) acc[mt][nt][r] = 0.f;

    gemm_load(sb, 0, 0, tid, m0, n0, Ah, Wh);

    for (int c = 0; c < 16; c++) {
        cp_wait0();
        __syncthreads();
        if (c + 1 < 16) gemm_load(sb, (c + 1) & 1, c + 1, tid, m0, n0, Ah, Wh);
        const uint32_t st = sb + (c & 1) * GSTAGE;
#pragma unroll
        for (int kt = 0; kt < 4; kt++) {
            uint32_t a_h[2][4];
#pragma unroll
            for (int mt = 0; mt < 2; mt++) {
                const uint32_t ra = st +
                    (uint32_t)(wm * 32 + mt * 16 + ((lane >> 3) & 1) * 8 + (lane & 7)) * GSTRIDE +
                    kt * 32 + (lane >> 4) * 16;
                ldsm4(a_h[mt], ra);
            }
#pragma unroll
            for (int hf = 0; hf < 2; hf++) {
                uint32_t b_h[2][4];
#pragma unroll
                for (int j = 0; j < 2; j++) {
                    const int nt2 = hf * 2 + j;
                    const uint32_t rb = st + GARR +
                        (uint32_t)(wn * 64 + nt2 * 16 + (lane >> 4) * 8 + (lane & 7)) * GSTRIDE +
                        kt * 32 + ((lane >> 3) & 1) * 16;
                    ldsm4(b_h[j], rb);
                }
#pragma unroll
                for (int mt = 0; mt < 2; mt++)
#pragma unroll
                    for (int j = 0; j < 2; j++) {
                        mma16816(acc[mt][(hf * 2 + j) * 2],     a_h[mt], b_h[j]);
                        mma16816(acc[mt][(hf * 2 + j) * 2 + 1], a_h[mt], b_h[j] + 2);
                    }
            }
        }
    }

    const int grp = lane >> 2, qc = lane & 3;
#pragma unroll
    for (int mt = 0; mt < 2; mt++) {
#pragma unroll
        for (int nt = 0; nt < 8; nt++) {
            const int row = m0 + wm * 32 + mt * 16 + grp;
            const int col = n0 + wn * 64 + nt * 8 + qc * 2;
            const float b0 = bias[col], b1 = bias[col + 1];
            float v0 = acc[mt][nt][0] + b0, v1 = acc[mt][nt][1] + b1;
            float v2 = acc[mt][nt][2] + b0, v3 = acc[mt][nt][3] + b1;
            if (MODE == 0) {
                *(float2*)&C[(size_t)row * Dm + col]       = make_float2(v0, v1);
                *(float2*)&C[(size_t)(row + 8) * Dm + col] = make_float2(v2, v3);
            } else {
                if (z == 0) { v0 *= 0.125f; v1 *= 0.125f; v2 *= 0.125f; v3 *= 0.125f; }
                const int hh = col >> 6, dk = col & 63;
#pragma unroll
                for (int half_i = 0; half_i < 2; half_i++) {
                    const int r2 = row + half_i * 8;
                    const int bb = r2 >> 11, s = r2 & 2047;
                    const size_t idx = (((size_t)(bb * Hh + hh)) * Ssz + s) * Dk + dk;
                    const float x0 = half_i ? v2 : v0, x1 = half_i ? v3 : v1;
                    *(uint32_t*)&Oh[idx] = pack_f16(x0, x1);
                }
            }
        }
    }
}

// ---------------- flash attention: f16-acc QK, f32-acc PV -------------------
#define FQ 128
#define FKS 128
#define FSTR 144
#define QH_OFF 0
#define KV_OFF 18432
#define KARR 18432
#define KVST 36864
#define VH_O 18432
#define FLASH_SMEM 92160

__device__ __forceinline__ void flash_load_kv(uint32_t sb, int j, int tid, size_t bh)
{
#pragma unroll
    for (int it = 0; it < 8; it++) {
        const int flat = it * 256 + tid;
        const int arr = flat >> 10, rem = flat & 1023;
        const int row = rem >> 3, seg = rem & 7;
        const __half* src = (arr == 0) ? g_kh : g_vh;
        cp16(sb + KV_OFF + (j & 1) * KVST + arr * KARR + row * FSTR + seg * 16,
             src + (bh * Ssz + j * FKS + row) * Dk + seg * 8);
    }
    cp_commit();
}

__global__ __launch_bounds__(256, 2)
void flash(const uint32_t* __restrict__ mb, __half* __restrict__ xh)
{
    extern __shared__ char smem[];
    const uint32_t sb = smem_u32(smem);
    const int tid = threadIdx.x, lane = tid & 31, w = tid >> 5;
    const int b = blockIdx.z, h = blockIdx.y, q0 = blockIdx.x * FQ;
    const size_t bh = (size_t)(b * Hh + h);
    const int grp = lane >> 2, qc = lane & 3;
    const int row_a = q0 + w * 16 + grp;

    flash_load_kv(sb, 0, tid, bh);
#pragma unroll
    for (int it = 0; it < 4; it++) {
        const int flat = it * 256 + tid;
        const int row = flat >> 3, seg = flat & 7;
        cp16(sb + QH_OFF + row * FSTR + seg * 16,
             g_qh + (bh * Ssz + q0 + row) * Dk + seg * 8);
    }
    cp_commit();
    cp_wait0();
    __syncthreads();

    const uint32_t qrow = (uint32_t)(w * 16 + ((lane >> 3) & 1) * 8 + (lane & 7)) * FSTR +
                          (lane >> 4) * 16;
    uint32_t qfh[4][4];
#pragma unroll
    for (int kt = 0; kt < 4; kt++) ldsm4(qfh[kt], sb + QH_OFF + qrow + kt * 32);

    float acc_o[8][4];
#pragma unroll
    for (int nt = 0; nt < 8; nt++)
#pragma unroll
        for (int r = 0; r < 4; r++) acc_o[nt][r] = 0.f;
    float m_a = -CUDART_INF_F, m_b = -CUDART_INF_F, l_a = 0.f, l_b = 0.f;

    const uint32_t* mrow_a = mb + ((size_t)b * Ssz + row_a) * (Ssz / 32);
    const uint32_t* mrow_b = mrow_a + 8 * (Ssz / 32);

    const int NJT = Ssz / FKS;   // 16
    for (int jt = 0; jt < NJT; jt++) {
        const uint4 wa = *(const uint4*)(mrow_a + jt * 4);
        const uint4 wb = *(const uint4*)(mrow_b + jt * 4);
        if (jt > 0) { cp_wait0(); __syncthreads(); }
        if (jt + 1 < NJT) flash_load_kv(sb, jt + 1, tid, bh);
        const uint32_t st = sb + KV_OFF + (jt & 1) * KVST;

#pragma unroll
        for (int half = 0; half < 2; half++) {
            const uint32_t kbase = st + (uint32_t)(half * 64) * FSTR;
            const uint32_t wax = half ? wa.z : wa.x, way = half ? wa.w : wa.y;
            const uint32_t wbx = half ? wb.z : wb.x, wby = half ? wb.w : wb.y;

            // ---- QK^T with fp16 accumulators ----
            uint32_t sh[8][2];
#pragma unroll
            for (int nt = 0; nt < 8; nt++) { sh[nt][0] = 0u; sh[nt][1] = 0u; }
#pragma unroll
            for (int kt = 0; kt < 4; kt++) {
#pragma unroll
                for (int hf = 0; hf < 2; hf++) {
                    uint32_t b_h[2][4];
#pragma unroll
                    for (int j = 0; j < 2; j++) {
                        const int nt2 = hf * 2 + j;
                        const uint32_t rb = kbase +
                            (uint32_t)(nt2 * 16 + (lane >> 4) * 8 + (lane & 7)) * FSTR +
                            kt * 32 + ((lane >> 3) & 1) * 16;
                        ldsm4(b_h[j], rb);
                    }
#pragma unroll
                    for (int j = 0; j < 2; j++) {
                        mma16816h(sh[(hf * 2 + j) * 2],     qfh[kt], b_h[j]);
                        mma16816h(sh[(hf * 2 + j) * 2 + 1], qfh[kt], b_h[j] + 2);
                    }
                }
            }
            // unpack fp16 scores -> fp32
            float s[8][4];
#pragma unroll
            for (int nt = 0; nt < 8; nt++) {
                const float2 f0 = __half22float2(*(const __half2*)&sh[nt][0]);
                const float2 f1 = __half22float2(*(const __half2*)&sh[nt][1]);
                s[nt][0] = f0.x; s[nt][1] = f0.y;
                s[nt][2] = f1.x; s[nt][3] = f1.y;
            }

            // ---- mask + online softmax ----
            float ra = -CUDART_INF_F, rbx = -CUDART_INF_F;
#pragma unroll
            for (int nt = 0; nt < 8; nt++) {
                const int kk = nt * 8 + qc * 2;
                const uint32_t wA = (nt < 4) ? wax : way;
                const uint32_t wB = (nt < 4) ? wbx : wby;
                const int bit = kk & 31;
                s[nt][0] = ((wA >> bit) & 1)       ? s[nt][0] : -1e9f;
                s[nt][1] = ((wA >> (bit + 1)) & 1) ? s[nt][1] : -1e9f;
                s[nt][2] = ((wB >> bit) & 1)       ? s[nt][2] : -1e9f;
                s[nt][3] = ((wB >> (bit + 1)) & 1) ? s[nt][3] : -1e9f;
                ra  = fmaxf(ra,  fmaxf(s[nt][0], s[nt][1]));
                rbx = fmaxf(rbx, fmaxf(s[nt][2], s[nt][3]));
            }
            ra = qmax(ra); rbx = qmax(rbx);
            const float mna = fmaxf(m_a, ra), mnb = fmaxf(m_b, rbx);
            const float ca = __expf(m_a - mna), cb = __expf(m_b - mnb);
            float suma = 0.f, sumb = 0.f;
#pragma unroll
            for (int nt = 0; nt < 8; nt++) {
                s[nt][0] = __expf(s[nt][0] - mna);
                s[nt][1] = __expf(s[nt][1] - mna);
                s[nt][2] = __expf(s[nt][2] - mnb);
                s[nt][3] = __expf(s[nt][3] - mnb);
                suma += s[nt][0] + s[nt][1];
                sumb += s[nt][2] + s[nt][3];
            }
            l_a = l_a * ca + qsum(suma);
            l_b = l_b * cb + qsum(sumb);
#pragma unroll
            for (int nt = 0; nt < 8; nt++) {
                acc_o[nt][0] *= ca; acc_o[nt][1] *= ca;
                acc_o[nt][2] *= cb; acc_o[nt][3] *= cb;
            }
            m_a = mna; m_b = mnb;

            // ---- P @ V (fp32 accumulators) ----
#pragma unroll
            for (int kt2 = 0; kt2 < 4; kt2++) {
                uint32_t p_h[4];
                p_h[0] = pack_f16(s[2 * kt2][0],     s[2 * kt2][1]);
                p_h[1] = pack_f16(s[2 * kt2][2],     s[2 * kt2][3]);
                p_h[2] = pack_f16(s[2 * kt2 + 1][0], s[2 * kt2 + 1][1]);
                p_h[3] = pack_f16(s[2 * kt2 + 1][2], s[2 * kt2 + 1][3]);
#pragma unroll
                for (int hf = 0; hf < 2; hf++) {
                    uint32_t v_h[2][4];
#pragma unroll
                    for (int j = 0; j < 2; j++) {
                        const int nd2 = hf * 2 + j;
                        const uint32_t vb = st + VH_O +
                            (uint32_t)(half * 64 + kt2 * 16 + ((lane >> 3) & 1) * 8 + (lane & 7)) * FSTR +
                            nd2 * 32 + (lane >> 4) * 16;
                        ldsm4t(v_h[j], vb);
                    }
#pragma unroll
                    for (int j = 0; j < 2; j++) {
                        mma16816(acc_o[(hf * 2 + j) * 2],     p_h, v_h[j]);
                        mma16816(acc_o[(hf * 2 + j) * 2 + 1], p_h, v_h[j] + 2);
                    }
                }
            }
        }
    }

    // epilogue: x hi-only fp16
    const float inva = 1.f / l_a, invb = 1.f / l_b;
#pragma unroll
    for (int nt = 0; nt < 8; nt++) {
        const int col = h * Dk + nt * 8 + qc * 2;
        size_t idx = ((size_t)b * Ssz + row_a) * Dm + col;
        *(uint32_t*)&xh[idx] = pack_f16(acc_o[nt][0] * inva, acc_o[nt][1] * inva);
        idx = ((size_t)b * Ssz + row_a + 8) * Dm + col;
        *(uint32_t*)&xh[idx] = pack_f16(acc_o[nt][2] * invb, acc_o[nt][3] * invb);
    }
}

// ---------------- launch ----------------------------------------------------
extern "C" void kernel_launch(void* const* d_in, const int* in_sizes, int n_in,
                              void* d_out, int out_size)
{
    (void)in_sizes; (void)n_in; (void)out_size;
    const float* query  = (const float*)d_in[0];
    const float* key_in = (const float*)d_in[1];
    const float* value  = (const float*)d_in[2];
    const int*   mask   = (const int*)  d_in[3];
    const float* Wq = (const float*)d_in[4];
    const float* bq = (const float*)d_in[5];
    const float* Wk = (const float*)d_in[6];
    const float* bk = (const float*)d_in[7];
    const float* Wv = (const float*)d_in[8];
    const float* bv = (const float*)d_in[9];
    const float* Wo = (const float*)d_in[10];
    const float* bo = (const float*)d_in[11];
    float* out = (float*)d_out;

    __half* ah;
    uint32_t* mbp;
    cudaGetSymbolAddress((void**)&ah, g_ah);
    cudaGetSymbolAddress((void**)&mbp, g_mb);

    cudaFuncSetAttribute(tgemm<0>, cudaFuncAttributeMaxDynamicSharedMemorySize, GEMM_SMEM);
    cudaFuncSetAttribute(tgemm<1>, cudaFuncAttributeMaxDynamicSharedMemorySize, GEMM_SMEM);
    cudaFuncSetAttribute(flash, cudaFuncAttributeMaxDynamicSharedMemorySize, FLASH_SMEM);

    prep_kernel<<<32768, 256>>>(query, key_in, value, mask, Wq, Wk, Wv, Wo);
    dim3 pgrid(Dm / 128, 8192 / 128, 3);
    tgemm<1><<<pgrid, 256, GEMM_SMEM>>>(bq, bk, bv, nullptr);
    dim3 fgrid(Ssz / FQ, Hh, Bsz);
    flash<<<fgrid, 256, FLASH_SMEM>>>(mbp, ah);
    dim3 ogrid(Dm / 128, 8192 / 128);
    tgemm<0><<<ogrid, 256, GEMM_SMEM>>>(bo, nullptr, nullptr, out);
}